// round 14
// baseline (speedup 1.0000x reference)
#include <cuda_runtime.h>
#include <cuda_bf16.h>
#include <math.h>
#include <stdint.h>

#define BATCH 1024
#define NDIM  8192
#define TM2   128
#define NSPLIT 16                 // loop nt split

#define NT_SMEM_BYTES 98304
#define NN_SMEM_BYTES 98304
#define AF_SMEM_BYTES 65536

// ---------------- scratch (static device globals; no runtime alloc) --------
__device__ float g_part[(size_t)8 * 2048 * TM2];
__device__ float g_d [BATCH * TM2];
__device__ float g_u [BATCH * TM2];
__device__ float g_M   [TM2 * TM2];
__device__ float g_G   [TM2 * TM2];
__device__ float g_S   [TM2 * TM2];
__device__ float g_NSa [TM2 * TM2];
__device__ float g_NSb [TM2 * TM2];
__device__ float g_HT  [TM2 * TM2];
__device__ uint32_t g_sfh[8 * 8192];
__device__ uint32_t g_sfl[8 * 8192];
__device__ uint32_t g_Xfh[(size_t)8 * 64 * 8192];
__device__ uint32_t g_Xfl[(size_t)8 * 64 * 8192];
__device__ uint32_t g_rnfh[(size_t)16 * 64 * 8192];
__device__ uint32_t g_rnfl[(size_t)16 * 64 * 8192];
__device__ uint32_t g_Wafh[64 * 8192];
__device__ uint32_t g_Wafl[64 * 8192];
__device__ uint32_t g_Wnfh[128 * 4096];
__device__ uint32_t g_Wnfl[128 * 4096];
__device__ uint32_t g_Wtfh[64 * 2 * 4096];
__device__ uint32_t g_Wtfl[64 * 2 * 4096];

// ---------------- helpers ----------------------------------------------------
__device__ __forceinline__ uint32_t pack_bf16x2(float a, float b) {
    uint32_t lo = (uint32_t)__bfloat16_as_ushort(__float2bfloat16(a));
    uint32_t hi = (uint32_t)__bfloat16_as_ushort(__float2bfloat16(b));
    return lo | (hi << 16);
}
__device__ __forceinline__ void mma16816(float* c, const uint4& a,
                                         const uint2& b) {
    asm("mma.sync.aligned.m16n8k16.row.col.f32.bf16.bf16.f32 "
        "{%0,%1,%2,%3}, {%4,%5,%6,%7}, {%8,%9}, {%0,%1,%2,%3};"
        : "+f"(c[0]), "+f"(c[1]), "+f"(c[2]), "+f"(c[3])
        : "r"(a.x), "r"(a.y), "r"(a.z), "r"(a.w), "r"(b.x), "r"(b.y));
}
__device__ __forceinline__ uint32_t a_addr(int row, int kp) {
    uint32_t tile = (uint32_t)((row >> 4) * 8 + (kp >> 3));
    uint32_t lane = ((row & 7) << 2) + (kp & 3);
    uint32_t reg = ((row >> 3) & 1) | (((kp >> 2) & 1) << 1);
    return tile * 128 + lane * 4 + reg;
}
__device__ __forceinline__ uint32_t b_addr(int n, int kp) {
    uint32_t tile = (uint32_t)((n >> 3) * 8 + (kp >> 3));
    uint32_t lane = ((n & 7) << 2) + (kp & 3);
    uint32_t reg = (kp >> 2) & 1;
    return tile * 64 + lane * 2 + reg;
}
__device__ __forceinline__ uint32_t smem_u32(const void* p) {
    uint32_t a;
    asm("{ .reg .u64 t; cvta.to.shared.u64 t, %1; cvt.u32.u64 %0, t; }"
        : "=r"(a) : "l"(p));
    return a;
}
__device__ __forceinline__ void cp16(uint32_t saddr, const void* g) {
    asm volatile("cp.async.cg.shared.global [%0], [%1], 16;"
                 :: "r"(saddr), "l"(g));
}

// ============================================================================
// nt2: part[split][r][j] = sum_{k in chunk} A[r,k] * W[j,k]
// cp.async double-buffered smem halves + register-pipelined A fragments.
// ============================================================================
__global__ void __launch_bounds__(256, 2)
nt2(const uint32_t* __restrict__ Afh, const uint32_t* __restrict__ Afl,
    float* __restrict__ part, int rows, int nsubs) {
    extern __shared__ uint32_t sm[];
    uint32_t sb = smem_u32(sm);
    const uint4* sA4h = (const uint4*)sm;
    const uint4* sA4l = (const uint4*)(sm + 8192);
    const uint2* sB2h = (const uint2*)(sm + 16384);
    const uint2* sB2l = (const uint2*)(sm + 20480);
    int tid = threadIdx.x;
    int lane = tid & 31, wid = tid >> 5;
    int wr = wid >> 1, wc = wid & 1;
    int rtile = blockIdx.x;
    int split = blockIdx.y;
    int jblk  = blockIdx.z;
    int r0 = rtile * 128;
    int q = lane & 3, g = lane >> 2;
    int H = nsubs * 2;

    float acc[2][4][4];
#pragma unroll
    for (int mt = 0; mt < 2; mt++)
#pragma unroll
        for (int nt = 0; nt < 4; nt++)
#pragma unroll
            for (int e = 0; e < 4; e++) acc[mt][nt][e] = 0.f;

#define NT2_FILL(h)                                                           \
    do {                                                                      \
        int ksub_ = split * nsubs + ((h) >> 1);                               \
        int s0_ = ((h) & 1) * 4;                                              \
        int buf_ = (h) & 1;                                                   \
        const uint4* gAh4 = (const uint4*)Afh                                 \
                            + ((size_t)rtile * 64 + ksub_) * 2048;            \
        const uint4* gAl4 = (const uint4*)Afl                                 \
                            + ((size_t)rtile * 64 + ksub_) * 2048;            \
        const uint4* gBh4 = (const uint4*)g_Wtfh                              \
                            + ((size_t)ksub_ * 2 + jblk) * 1024;              \
        const uint4* gBl4 = (const uint4*)g_Wtfl                              \
                            + ((size_t)ksub_ * 2 + jblk) * 1024;              \
        _Pragma("unroll")                                                     \
        for (int j_ = 0; j_ < 4; j_++) {                                      \
            int i_ = tid + j_ * 256;                                          \
            int seg_ = i_ >> 5, e_ = i_ & 31;                                 \
            int rg_ = seg_ >> 2, tl_ = seg_ & 3;                              \
            const uint4* sh_ = gAh4 + (rg_ * 8 + s0_ + tl_) * 32 + e_;        \
            const uint4* sl_ = gAl4 + (rg_ * 8 + s0_ + tl_) * 32 + e_;        \
            cp16(sb + buf_ * 16384 + i_ * 16, sh_);                           \
            cp16(sb + 32768 + buf_ * 16384 + i_ * 16, sl_);                   \
        }                                                                     \
        _Pragma("unroll")                                                     \
        for (int j_ = 0; j_ < 2; j_++) {                                      \
            int i_ = tid + j_ * 256;                                          \
            int seg_ = i_ >> 4, e_ = i_ & 15;                                 \
            int ng_ = seg_ >> 2, tl_ = seg_ & 3;                              \
            const uint4* sh_ = gBh4 + (ng_ * 8 + s0_ + tl_) * 16 + e_;        \
            const uint4* sl_ = gBl4 + (ng_ * 8 + s0_ + tl_) * 16 + e_;        \
            cp16(sb + 65536 + buf_ * 8192 + i_ * 16, sh_);                    \
            cp16(sb + 81920 + buf_ * 8192 + i_ * 16, sl_);                    \
        }                                                                     \
        asm volatile("cp.async.commit_group;" ::: "memory");                  \
    } while (0)

    NT2_FILL(0);
    for (int h = 0; h < H; h++) {
        if (h + 1 < H) {
            NT2_FILL(h + 1);
            asm volatile("cp.async.wait_group 1;" ::: "memory");
        } else {
            asm volatile("cp.async.wait_group 0;" ::: "memory");
        }
        __syncthreads();
        int buf = h & 1;
        // register-pipelined A fragments (B loaded just-in-time)
        uint4 pah[2][2], pal[2][2];
#pragma unroll
        for (int mt = 0; mt < 2; mt++) {
            uint32_t i4 = (uint32_t)(buf * 1024 + ((wr * 2 + mt) * 4) * 32 + lane);
            pah[0][mt] = sA4h[i4];
            pal[0][mt] = sA4l[i4];
        }
#pragma unroll
        for (int s = 0; s < 4; s++) {
            int cb = s & 1;
            if (s < 3) {
#pragma unroll
                for (int mt = 0; mt < 2; mt++) {
                    uint32_t i4 = (uint32_t)(buf * 1024
                                   + ((wr * 2 + mt) * 4 + s + 1) * 32 + lane);
                    pah[cb ^ 1][mt] = sA4h[i4];
                    pal[cb ^ 1][mt] = sA4l[i4];
                }
            }
            uint2 bh[4], bl[4];
#pragma unroll
            for (int nt = 0; nt < 4; nt++) {
                uint32_t i2 = (uint32_t)(buf * 1024
                               + ((wc * 4 + nt) * 4 + s) * 32 + lane);
                bh[nt] = sB2h[i2];
                bl[nt] = sB2l[i2];
            }
#pragma unroll
            for (int mt = 0; mt < 2; mt++)
#pragma unroll
                for (int nt = 0; nt < 4; nt++)
                    mma16816(acc[mt][nt], pah[cb][mt], bh[nt]);
#pragma unroll
            for (int mt = 0; mt < 2; mt++)
#pragma unroll
                for (int nt = 0; nt < 4; nt++)
                    mma16816(acc[mt][nt], pah[cb][mt], bl[nt]);
#pragma unroll
            for (int mt = 0; mt < 2; mt++)
#pragma unroll
                for (int nt = 0; nt < 4; nt++)
                    mma16816(acc[mt][nt], pal[cb][mt], bh[nt]);
        }
        __syncthreads();
    }
#undef NT2_FILL

    float* pb = part + ((size_t)split * rows + r0) * TM2;
#pragma unroll
    for (int mt = 0; mt < 2; mt++) {
        int row = wr * 32 + mt * 16 + g;
#pragma unroll
        for (int nt = 0; nt < 4; nt++) {
            int col = jblk * 64 + wc * 32 + nt * 8 + 2 * q;
            *(float2*)&pb[(size_t)row * TM2 + col] =
                make_float2(acc[mt][nt][0], acc[mt][nt][1]);
            *(float2*)&pb[(size_t)(row + 8) * TM2 + col] =
                make_float2(acc[mt][nt][2], acc[mt][nt][3]);
        }
    }
}

// deterministic fixed-order split reduction (for W W^T only)
__global__ void reduce_nt(const float4* __restrict__ part,
                          float4* __restrict__ out, int count4, int nsplit) {
    int i = blockIdx.x * 256 + threadIdx.x;
    if (i < count4) {
        float4 s = make_float4(0.f, 0.f, 0.f, 0.f);
        for (int k = 0; k < nsplit; k++) {
            float4 v = part[(size_t)k * count4 + i];
            s.x += v.x; s.y += v.y; s.z += v.z; s.w += v.w;
        }
        out[i] = s;
    }
}

// ============================================================================
// nn2: X[b,n] = relu(rn_r[b,n] + sum_k s[b,k] * W[k,n]); K = 128.
// Fully register-pipelined fragment loads.
// ============================================================================
__global__ void __launch_bounds__(256, 2)
mma_nn2(const float* __restrict__ rn, float* __restrict__ outx, int final_out) {
    extern __shared__ uint32_t sm[];
    uint32_t* sAh = sm;
    uint32_t* sAl = sm + 8192;
    uint32_t* sBh = sm + 16384;
    uint32_t* sBl = sm + 20480;
    int tid = threadIdx.x;
    int lane = tid & 31, wid = tid >> 5;
    int wr = wid >> 1, wc = wid & 1;
    int nblk = blockIdx.x;
    int rtile = blockIdx.y;
    int n0 = nblk * 64;
    int r0 = rtile * 128;
    int q = lane & 3, g = lane >> 2;

    {
        const uint4* gAh = (const uint4*)g_sfh + (size_t)rtile * 2048;
        const uint4* gAl = (const uint4*)g_sfl + (size_t)rtile * 2048;
        const uint4* gBh = (const uint4*)g_Wnfh + (size_t)nblk * 1024;
        const uint4* gBl = (const uint4*)g_Wnfl + (size_t)nblk * 1024;
#pragma unroll
        for (int i = 0; i < 8; i++) {
            ((uint4*)sAh)[tid + i * 256] = gAh[tid + i * 256];
            ((uint4*)sAl)[tid + i * 256] = gAl[tid + i * 256];
        }
#pragma unroll
        for (int i = 0; i < 4; i++) {
            ((uint4*)sBh)[tid + i * 256] = gBh[tid + i * 256];
            ((uint4*)sBl)[tid + i * 256] = gBl[tid + i * 256];
        }
    }
    __syncthreads();

    float acc[2][4][4];
#pragma unroll
    for (int mt = 0; mt < 2; mt++)
#pragma unroll
        for (int nt = 0; nt < 4; nt++)
#pragma unroll
            for (int e = 0; e < 4; e++) acc[mt][nt][e] = 0.f;

    uint4 ah[2][2], al[2][2];
    uint2 bh[2][4], bl[2][4];
#define NN_LOAD(pb, s)                                                        \
    do {                                                                      \
        _Pragma("unroll")                                                     \
        for (int mt_ = 0; mt_ < 2; mt_++) {                                   \
            uint32_t i4 = (uint32_t)(((wr * 2 + mt_) * 8 + (s)) * 32 + lane); \
            ah[pb][mt_] = ((const uint4*)sAh)[i4];                            \
            al[pb][mt_] = ((const uint4*)sAl)[i4];                            \
        }                                                                     \
        _Pragma("unroll")                                                     \
        for (int nt_ = 0; nt_ < 4; nt_++) {                                   \
            uint32_t i2 = (uint32_t)(((wc * 4 + nt_) * 8 + (s)) * 32 + lane); \
            bh[pb][nt_] = ((const uint2*)sBh)[i2];                            \
            bl[pb][nt_] = ((const uint2*)sBl)[i2];                            \
        }                                                                     \
    } while (0)

    NN_LOAD(0, 0);
#pragma unroll
    for (int s = 0; s < 8; s++) {
        int cb = s & 1;
        if (s < 7) NN_LOAD(cb ^ 1, s + 1);
#pragma unroll
        for (int mt = 0; mt < 2; mt++)
#pragma unroll
            for (int nt = 0; nt < 4; nt++)
                mma16816(acc[mt][nt], ah[cb][mt], bh[cb][nt]);
#pragma unroll
        for (int mt = 0; mt < 2; mt++)
#pragma unroll
            for (int nt = 0; nt < 4; nt++)
                mma16816(acc[mt][nt], ah[cb][mt], bl[cb][nt]);
#pragma unroll
        for (int mt = 0; mt < 2; mt++)
#pragma unroll
            for (int nt = 0; nt < 4; nt++)
                mma16816(acc[mt][nt], al[cb][mt], bh[cb][nt]);
    }
#undef NN_LOAD

    int ksub = nblk >> 1;
    uint32_t* gxh = g_Xfh + ((size_t)rtile * 64 + ksub) * 8192;
    uint32_t* gxl = g_Xfl + ((size_t)rtile * 64 + ksub) * 8192;
    float2 zero2 = make_float2(0.f, 0.f);
#pragma unroll
    for (int mt = 0; mt < 2; mt++) {
        int rowbase = wr * 32 + mt * 16 + g;
#pragma unroll
        for (int nt = 0; nt < 4; nt++) {
            int col = wc * 32 + nt * 8 + 2 * q;
            int kp = ((nblk & 1) << 5) + (col >> 1);
#pragma unroll
            for (int half = 0; half < 2; half++) {
                int row = rowbase + half * 8;
                int r = r0 + row;
                int n = n0 + col;
                float2 rv = *(const float2*)(rn + (size_t)r * (2 * NDIM) + n);
                float c0 = fmaxf(acc[mt][nt][half * 2 + 0] + rv.x, 0.f);
                float c1 = fmaxf(acc[mt][nt][half * 2 + 1] + rv.y, 0.f);
                float h0 = __bfloat162float(__float2bfloat16(c0));
                float h1 = __bfloat162float(__float2bfloat16(c1));
                uint32_t ad = a_addr(row, kp);
                gxh[ad] = pack_bf16x2(c0, c1);
                gxl[ad] = pack_bf16x2(c0 - h0, c1 - h1);
                if (final_out) {
                    size_t base = (size_t)r * (2 * NDIM);
                    *(float2*)(outx + base + n) = make_float2(c0, c1);
                    *(float2*)(outx + base + NDIM + n) = zero2;
                }
            }
        }
    }
}

// ---------------- fp32 -> A-fragment conversion (smem-staged) ---------------
__global__ void to_afrag(const float* __restrict__ src,
                         uint32_t* __restrict__ dfh,
                         uint32_t* __restrict__ dfl) {
    extern __shared__ uint32_t sm[];
    uint32_t* sh = sm;
    uint32_t* sl = sm + 8192;
    int tid = threadIdx.x;
    int rtile = blockIdx.x, ksub = blockIdx.y;
#pragma unroll
    for (int i = 0; i < 32; i++) {
        int idx = tid + i * 256;
        int rowl = idx >> 6, kpl = idx & 63;
        float2 v = *(const float2*)(src
                    + (size_t)(rtile * 128 + rowl) * NDIM + ksub * 128 + 2 * kpl);
        float h0 = __bfloat162float(__float2bfloat16(v.x));
        float h1 = __bfloat162float(__float2bfloat16(v.y));
        uint32_t ad = a_addr(rowl, kpl);
        sh[ad] = pack_bf16x2(v.x, v.y);
        sl[ad] = pack_bf16x2(v.x - h0, v.y - h1);
    }
    __syncthreads();
    size_t base = ((size_t)rtile * 64 + ksub) * 2048;
#pragma unroll
    for (int i = 0; i < 8; i++) {
        ((uint4*)dfh)[base + tid + i * 256] = ((const uint4*)sh)[tid + i * 256];
        ((uint4*)dfl)[base + tid + i * 256] = ((const uint4*)sl)[tid + i * 256];
    }
}

// ---------------- W B-fragment precomputes ----------------------------------
__global__ void wf_nn(const float* __restrict__ W) {
    int idx = blockIdx.x * 256 + threadIdx.x;
    if (idx < 8192 * 64) {
        int n = idx >> 6, kp = idx & 63;
        float v0 = W[(size_t)(2 * kp) * NDIM + n];
        float v1 = W[(size_t)(2 * kp + 1) * NDIM + n];
        float h0 = __bfloat162float(__float2bfloat16(v0));
        float h1 = __bfloat162float(__float2bfloat16(v1));
        int nblk = n >> 6, nl = n & 63;
        uint32_t ad = (uint32_t)nblk * 4096 + b_addr(nl, kp);
        g_Wnfh[ad] = pack_bf16x2(v0, v1);
        g_Wnfl[ad] = pack_bf16x2(v0 - h0, v1 - h1);
    }
}
__global__ void wf_nt(const float* __restrict__ W) {
    int idx = blockIdx.x * 256 + threadIdx.x;
    if (idx < 128 * 4096) {
        int j = idx >> 12, k2 = idx & 4095;
        float v0 = W[(size_t)j * NDIM + 2 * k2];
        float v1 = W[(size_t)j * NDIM + 2 * k2 + 1];
        float h0 = __bfloat162float(__float2bfloat16(v0));
        float h1 = __bfloat162float(__float2bfloat16(v1));
        int ksub = k2 >> 6, kpl = k2 & 63;
        int jblk = j >> 6, jl = j & 63;
        uint32_t ad = (uint32_t)(ksub * 2 + jblk) * 4096 + b_addr(jl, kpl);
        g_Wtfh[ad] = pack_bf16x2(v0, v1);
        g_Wtfl[ad] = pack_bf16x2(v0 - h0, v1 - h1);
    }
}

// ---------------- build G and S = G + I/rho ---------------------------------
__global__ void build_S(const float* __restrict__ log_rho) {
    int idx = blockIdx.x * blockDim.x + threadIdx.x;
    float inv_rho = 1.f / (expf(log_rho[0]) + 1e-12f);
    int p = idx >> 7, q = idx & 127;
    float sgn = ((p < 64) == (q < 64)) ? 1.f : -1.f;
    float g = g_M[idx] + sgn * g_M[((p ^ 64) << 7) + (q ^ 64)];
    g_G[idx] = g;
    g_S[idx] = g + ((p == q) ? inv_rho : 0.f);
}

// ---------------- Newton-Schulz inverse -------------------------------------
__global__ void gersh_initX1() {
    __shared__ float smax[4], smin[4], s_x0;
    int i = threadIdx.x;
    float rs = 0.f, dg = 0.f;
#pragma unroll 8
    for (int k = 0; k < 128; k++) {
        float v = g_S[i * 128 + k];
        rs += fabsf(v);
        if (k == i) dg = v;
    }
    float lo = 2.f * dg - rs;
    float mx = rs, mn = lo;
#pragma unroll
    for (int o = 16; o > 0; o >>= 1) {
        mx = fmaxf(mx, __shfl_down_sync(0xffffffffu, mx, o));
        mn = fminf(mn, __shfl_down_sync(0xffffffffu, mn, o));
    }
    if ((i & 31) == 0) { smax[i >> 5] = mx; smin[i >> 5] = mn; }
    __syncthreads();
    if (i == 0) {
        float lmax = fmaxf(fmaxf(smax[0], smax[1]), fmaxf(smax[2], smax[3]));
        float lmin = fminf(fminf(smin[0], smin[1]), fminf(smin[2], smin[3]));
        s_x0 = (lmin > 0.f) ? 2.f / (lmax + lmin) : 1.f / lmax;
    }
    __syncthreads();
    float x0 = s_x0;
    for (int e = i; e < 128 * 128; e += 128) {
        int p = e >> 7, q = e & 127;
        g_NSa[e] = 2.f * x0 * ((p == q) ? 1.f : 0.f) - x0 * x0 * g_S[e];
    }
}
__global__ void __launch_bounds__(256)
ns_step(const float* __restrict__ X, float* __restrict__ Xn) {
    __shared__ float xr[2][128];
    __shared__ float t[2][128];
    int tid = threadIdx.x;
    int r0 = blockIdx.x * 2;
    int rr = tid >> 7, j = tid & 127;
    xr[rr][j] = X[(r0 + rr) * 128 + j];
    __syncthreads();
    float acc = 0.f;
#pragma unroll 8
    for (int k = 0; k < 128; k++)
        acc = fmaf(xr[rr][k], g_S[k * 128 + j], acc);
    t[rr][j] = acc;
    __syncthreads();
    float acc2 = 0.f;
#pragma unroll 8
    for (int k = 0; k < 128; k++)
        acc2 = fmaf(t[rr][k], X[k * 128 + j], acc2);
    Xn[(r0 + rr) * 128 + j] = 2.f * xr[rr][j] - acc2;
}

// fused: blocks 0-127 -> HT rows; blocks 128-255 -> d = Sinv @ c
__global__ void HT_d(const float* __restrict__ Sinv,
                     const float* __restrict__ log_rho) {
    int tid = threadIdx.x;
    if (blockIdx.x < 128) {
        __shared__ float gk[128];
        int j = tid, k = blockIdx.x;
        float rho = expf(log_rho[0]);
        gk[j] = g_G[k * 128 + j];
        __syncthreads();
        float acc = 0.f;
#pragma unroll 4
        for (int m = 0; m < 128; m++)
            acc = fmaf(Sinv[m * 128 + j], gk[m], acc);
        g_HT[k * 128 + j] = rho * (((j == k) ? 1.f : 0.f) - acc);
    } else {
        __shared__ float cb[8][128];
        int b0 = (blockIdx.x - 128) * 8;
#pragma unroll
        for (int bb = 0; bb < 8; bb++) {
            int b = b0 + bb;
            float pa = 0.f, pbv = 0.f;
#pragma unroll
            for (int sp = 0; sp < 8; sp++) {
                pa  += g_part[((size_t)sp * 2048 + 2 * b) * TM2 + tid];
                pbv += g_part[((size_t)sp * 2048 + 2 * b + 1) * TM2 + (tid ^ 64)];
            }
            cb[bb][tid] = (tid < 64) ? pa - pbv : pa + pbv;
        }
        __syncthreads();
        float acc[8];
#pragma unroll
        for (int bb = 0; bb < 8; bb++) acc[bb] = 0.f;
        for (int k = 0; k < 128; k++) {
            float sv = Sinv[k * 128 + tid];
#pragma unroll
            for (int bb = 0; bb < 8; bb++) acc[bb] = fmaf(sv, cb[bb][k], acc[bb]);
        }
#pragma unroll
        for (int bb = 0; bb < 8; bb++)
            g_d[(b0 + bb) * TM2 + tid] = acc[bb];
    }
}

// s for iter 0: w = y - u_in; s = H w - d (frag output); init g_u
__global__ void s_init(const float* __restrict__ y,
                       const float* __restrict__ u_in) {
    __shared__ float w[8][128];
    int tid = threadIdx.x;
    int b0 = blockIdx.x * 8;
#pragma unroll
    for (int bb = 0; bb < 8; bb++) {
        float uv = u_in[(b0 + bb) * TM2 + tid];
        g_u[(b0 + bb) * TM2 + tid] = uv;
        w[bb][tid] = y[(b0 + bb) * TM2 + tid] - uv;
    }
    __syncthreads();
    float acc[8];
#pragma unroll
    for (int bb = 0; bb < 8; bb++) acc[bb] = 0.f;
    for (int k = 0; k < 128; k++) {
        float h = g_HT[k * 128 + tid];
#pragma unroll
        for (int bb = 0; bb < 8; bb++) acc[bb] = fmaf(h, w[bb][k], acc[bb]);
    }
    __syncthreads();
#pragma unroll
    for (int bb = 0; bb < 8; bb++)
        w[bb][tid] = acc[bb] - g_d[(b0 + bb) * TM2 + tid];
    __syncthreads();
    if (tid < 64) {
#pragma unroll
        for (int bb = 0; bb < 8; bb++) {
            int b = b0 + bb;
            int row = b & 127, rtile = b >> 7, kp = tid;
            float s0 = w[bb][2 * kp], s1 = w[bb][2 * kp + 1];
            float h0 = __bfloat162float(__float2bfloat16(s0));
            float h1 = __bfloat162float(__float2bfloat16(s1));
            uint32_t ad = (uint32_t)rtile * 8192 + a_addr(row, kp);
            g_sfh[ad] = pack_bf16x2(s0, s1);
            g_sfl[ad] = pack_bf16x2(s0 - h0, s1 - h1);
        }
    }
}

// fused: P = reduce(partials); zu update; s(frag) for next iter / final u out
__global__ void zus(const float* __restrict__ y,
                    const float* __restrict__ log_eps, int compute_s,
                    float* __restrict__ uout) {
    __shared__ float red[4];
    __shared__ float w[128];
    int b = blockIdx.x;
    int j = threadIdx.x;
    float eps = expf(log_eps[0]);
    float Pv = 0.f;
#pragma unroll
    for (int ks = 0; ks < NSPLIT; ks++)
        Pv += g_part[((size_t)ks * BATCH + b) * TM2 + j];
    float uv = g_u[b * TM2 + j];
    float yv = y[b * TM2 + j];
    float v = Pv + uv - yv;
    float t = v * v;
#pragma unroll
    for (int o = 16; o > 0; o >>= 1) t += __shfl_down_sync(0xffffffffu, t, o);
    if ((j & 31) == 0) red[j >> 5] = t;
    __syncthreads();
    float nrm = sqrtf(red[0] + red[1] + red[2] + red[3]);
    float scale = fminf(1.f, eps / (nrm + 1e-12f));
    float zv = yv + v * scale;
    float un = uv + Pv - zv;
    if (compute_s) {
        g_u[b * TM2 + j] = un;
        w[j] = zv - un;
        __syncthreads();
        float acc = 0.f;
#pragma unroll 4
        for (int k = 0; k < 128; k++)
            acc = fmaf(g_HT[k * 128 + j], w[k], acc);
        float sval = acc - g_d[b * TM2 + j];
        __syncthreads();
        w[j] = sval;
        __syncthreads();
        if (j < 64) {
            int row = b & 127, rtile = b >> 7, kp = j;
            float s0 = w[2 * kp], s1 = w[2 * kp + 1];
            float h0 = __bfloat162float(__float2bfloat16(s0));
            float h1 = __bfloat162float(__float2bfloat16(s1));
            uint32_t ad = (uint32_t)rtile * 8192 + a_addr(row, kp);
            g_sfh[ad] = pack_bf16x2(s0, s1);
            g_sfl[ad] = pack_bf16x2(s0 - h0, s1 - h1);
        }
    } else {
        uout[(size_t)BATCH * 2 * NDIM + b * TM2 + j] = un;
    }
}

// ---------------- launch ----------------------------------------------------
extern "C" void kernel_launch(void* const* d_in, const int* in_sizes, int n_in,
                              void* d_out, int out_size) {
    const float* rn   = (const float*)d_in[0];
    const float* y    = (const float*)d_in[1];
    const float* u_in = (const float*)d_in[2];
    const float* A    = (const float*)d_in[3];
    const float* lrho = (const float*)d_in[4];
    const float* leps = (const float*)d_in[5];
    float* out = (float*)d_out;
    (void)in_sizes; (void)n_in; (void)out_size;

    float *dM, *dPart, *dNSa, *dNSb;
    uint32_t *dWafh, *dWafl, *drnfh, *drnfl, *dXfh, *dXfl;
    cudaGetSymbolAddress((void**)&dM,    g_M);
    cudaGetSymbolAddress((void**)&dPart, g_part);
    cudaGetSymbolAddress((void**)&dNSa,  g_NSa);
    cudaGetSymbolAddress((void**)&dNSb,  g_NSb);
    cudaGetSymbolAddress((void**)&dWafh, g_Wafh);
    cudaGetSymbolAddress((void**)&dWafl, g_Wafl);
    cudaGetSymbolAddress((void**)&drnfh, g_rnfh);
    cudaGetSymbolAddress((void**)&drnfl, g_rnfl);
    cudaGetSymbolAddress((void**)&dXfh,  g_Xfh);
    cudaGetSymbolAddress((void**)&dXfl,  g_Xfl);

    static int attr_set = 0;
    if (!attr_set) {
        cudaFuncSetAttribute(nt2, cudaFuncAttributeMaxDynamicSharedMemorySize,
                             NT_SMEM_BYTES);
        cudaFuncSetAttribute(mma_nn2,
                             cudaFuncAttributeMaxDynamicSharedMemorySize,
                             NN_SMEM_BYTES);
        cudaFuncSetAttribute(to_afrag,
                             cudaFuncAttributeMaxDynamicSharedMemorySize,
                             AF_SMEM_BYTES);
        attr_set = 1;
    }

    // W fragment layouts + A-frag conversions
    wf_nn<<<(8192 * 64 + 255) / 256, 256>>>(A);
    wf_nt<<<(128 * 4096 + 255) / 256, 256>>>(A);
    to_afrag<<<dim3(1, 64), 256, AF_SMEM_BYTES>>>(A, dWafh, dWafl);
    to_afrag<<<dim3(16, 64), 256, AF_SMEM_BYTES>>>(rn, drnfh, drnfl);

    // M = W W^T (32-way split), then S
    nt2<<<dim3(1, 32, 2), 256, NT_SMEM_BYTES>>>(dWafh, dWafl, dPart, 128, 2);
    reduce_nt<<<(4096 + 255) / 256, 256>>>((const float4*)dPart,
                                           (float4*)dM, 4096, 32);
    build_S<<<64, 256>>>(lrho);

    // Newton-Schulz inverse: X1 + 3 fused steps
    gersh_initX1<<<1, 128>>>();
    ns_step<<<64, 256>>>(dNSa, dNSb);
    ns_step<<<64, 256>>>(dNSb, dNSa);
    ns_step<<<64, 256>>>(dNSa, dNSb);
    const float* Sinv = dNSb;

    // rn projections (2048 rows, 8-way split), fused HT + d, then s iter 0
    nt2<<<dim3(16, 8, 2), 256, NT_SMEM_BYTES>>>(drnfh, drnfl, dPart, 2048, 8);
    HT_d<<<256, 128>>>(Sinv, lrho);
    s_init<<<128, 128>>>(y, u_in);

    for (int it = 0; it < 3; it++) {
        int fin = (it == 2);
        mma_nn2<<<dim3(128, 8), 256, NN_SMEM_BYTES>>>(rn, out, fin);
        nt2<<<dim3(8, NSPLIT, 2), 256, NT_SMEM_BYTES>>>(dXfh, dXfl, dPart,
                                                        BATCH, 64 / NSPLIT);
        zus<<<BATCH, 128>>>(y, leps, it < 2, out);
    }
}

// round 15
// speedup vs baseline: 1.0647x; 1.0647x over previous
#include <cuda_runtime.h>
#include <cuda_bf16.h>
#include <math.h>
#include <stdint.h>

#define BATCH 1024
#define NDIM  8192
#define TM2   128
#define NSPLIT 16

#define NT_SMEM_BYTES 98304
#define AF_SMEM_BYTES 65536
#define FX_SMEM_BYTES 147456      // fused kernel: 144KB

// ---------------- scratch (static device globals; no runtime alloc) --------
__device__ float g_part[(size_t)8 * 2048 * TM2];     // 8MB (max of all users)
__device__ float g_d [BATCH * TM2];
__device__ float g_u [BATCH * TM2];
__device__ float g_M   [TM2 * TM2];
__device__ float g_G   [TM2 * TM2];
__device__ float g_S   [TM2 * TM2];
__device__ float g_NSa [TM2 * TM2];
__device__ float g_NSb [TM2 * TM2];
__device__ float g_HT  [TM2 * TM2];
__device__ uint32_t g_sfh[8 * 8192];                 // s A-frags [rtile][8192]
__device__ uint32_t g_sfl[8 * 8192];
__device__ uint32_t g_rnfh[(size_t)16 * 64 * 8192];  // rn A-frags [rtile][ksub]
__device__ uint32_t g_rnfl[(size_t)16 * 64 * 8192];
__device__ uint32_t g_Wafh[64 * 8192];               // W A-frags [ksub]
__device__ uint32_t g_Wafl[64 * 8192];
__device__ uint32_t g_Wnfh[128 * 4096];              // nn B-frags (n-hierarchical)
__device__ uint32_t g_Wnfl[128 * 4096];
__device__ uint32_t g_Wtfh[64 * 2 * 4096];           // nt B-frags [ksub][jblk]
__device__ uint32_t g_Wtfl[64 * 2 * 4096];

// ---------------- helpers ----------------------------------------------------
__device__ __forceinline__ uint32_t pack_bf16x2(float a, float b) {
    uint32_t lo = (uint32_t)__bfloat16_as_ushort(__float2bfloat16(a));
    uint32_t hi = (uint32_t)__bfloat16_as_ushort(__float2bfloat16(b));
    return lo | (hi << 16);
}
__device__ __forceinline__ void split_pack(float a, float b,
                                           uint32_t& hi, uint32_t& lo) {
    float ha = __bfloat162float(__float2bfloat16(a));
    float hb = __bfloat162float(__float2bfloat16(b));
    hi = pack_bf16x2(a, b);
    lo = pack_bf16x2(a - ha, b - hb);
}
__device__ __forceinline__ void mma16816(float* c, const uint4& a,
                                         const uint2& b) {
    asm("mma.sync.aligned.m16n8k16.row.col.f32.bf16.bf16.f32 "
        "{%0,%1,%2,%3}, {%4,%5,%6,%7}, {%8,%9}, {%0,%1,%2,%3};"
        : "+f"(c[0]), "+f"(c[1]), "+f"(c[2]), "+f"(c[3])
        : "r"(a.x), "r"(a.y), "r"(a.z), "r"(a.w), "r"(b.x), "r"(b.y));
}
__device__ __forceinline__ uint32_t a_addr(int row, int kp) {
    uint32_t tile = (uint32_t)((row >> 4) * 8 + (kp >> 3));
    uint32_t lane = ((row & 7) << 2) + (kp & 3);
    uint32_t reg = ((row >> 3) & 1) | (((kp >> 2) & 1) << 1);
    return tile * 128 + lane * 4 + reg;
}
__device__ __forceinline__ uint32_t b_addr(int n, int kp) {
    uint32_t tile = (uint32_t)((n >> 3) * 8 + (kp >> 3));
    uint32_t lane = ((n & 7) << 2) + (kp & 3);
    uint32_t reg = (kp >> 2) & 1;
    return tile * 64 + lane * 2 + reg;
}
__device__ __forceinline__ uint32_t smem_u32(const void* p) {
    uint32_t a;
    asm("{ .reg .u64 t; cvta.to.shared.u64 t, %1; cvt.u32.u64 %0, t; }"
        : "=r"(a) : "l"(p));
    return a;
}
__device__ __forceinline__ void cp16(uint32_t saddr, const void* g) {
    asm volatile("cp.async.cg.shared.global [%0], [%1], 16;"
                 :: "r"(saddr), "l"(g));
}

// ============================================================================
// FUSED loop kernel: X = relu(rn + s W) computed per 32-n slice and
// immediately consumed by P += X W^T. X never touches DRAM.
// grid (16 splits, 8 rtiles), 512 threads (16 warps: wr=wid>>2, wc=wid&3).
// smem: s frags 64KB + Wn 2x16KB + Wt 2x16KB + X staging 16KB = 144KB.
// ============================================================================
__global__ void __launch_bounds__(512, 1)
fused_xp(const float* __restrict__ rn, float* __restrict__ outx,
         int final_out, float* __restrict__ part) {
    extern __shared__ uint32_t sm[];
    uint32_t sb = smem_u32(sm);
    const uint4* sS4h = (const uint4*)sm;                  // 2048 uint4
    const uint4* sS4l = (const uint4*)(sm + 8192);
    int tid = threadIdx.x;
    int lane = tid & 31, wid = tid >> 5;
    int wr = wid >> 2, wc = wid & 3;
    int split = blockIdx.x;        // 0..15 -> 512 n per block
    int rtile = blockIdx.y;        // 0..7
    int r0 = rtile * 128;
    int q = lane & 3, g = lane >> 2;

    // persistent s fragment tiles (128 rows x 64 kp, hi/lo)
    {
        const uint4* gh = (const uint4*)g_sfh + (size_t)rtile * 2048;
        const uint4* gl = (const uint4*)g_sfl + (size_t)rtile * 2048;
#pragma unroll
        for (int i = 0; i < 4; i++) {
            ((uint4*)sm)[tid + i * 512] = gh[tid + i * 512];
            ((uint4*)(sm + 8192))[tid + i * 512] = gl[tid + i * 512];
        }
    }

    float P[2][4][4];
#pragma unroll
    for (int mt = 0; mt < 2; mt++)
#pragma unroll
        for (int ntj = 0; ntj < 4; ntj++)
#pragma unroll
            for (int e = 0; e < 4; e++) P[mt][ntj][e] = 0.f;

    // fill macro: slice h -> buffer (h&1). Wn contiguous; Wt strided slice.
#define FX_FILL(h)                                                            \
    do {                                                                      \
        int nh_ = split * 16 + (h);                                           \
        int buf_ = (h) & 1;                                                   \
        const uint4* gnh = (const uint4*)g_Wnfh + (size_t)nh_ * 512;          \
        const uint4* gnl = (const uint4*)g_Wnfl + (size_t)nh_ * 512;          \
        cp16(sb + 65536 + buf_ * 16384 + tid * 16, gnh + tid);                \
        cp16(sb + 73728 + buf_ * 16384 + tid * 16, gnl + tid);                \
        int ksub_ = nh_ >> 2;                                                 \
        int kt0_ = (nh_ & 3) * 2;                                             \
        {                                                                     \
            int jblk_ = tid >> 8;                                             \
            int rem_ = tid & 255;                                             \
            int jt_ = rem_ >> 5, e_ = rem_ & 31;                              \
            size_t src_ = ((size_t)ksub_ * 2 + jblk_) * 1024 + jt_ * 128      \
                          + kt0_ * 16 + e_;                                   \
            cp16(sb + 98304 + buf_ * 16384 + tid * 16,                        \
                 (const uint4*)g_Wtfh + src_);                                \
            cp16(sb + 106496 + buf_ * 16384 + tid * 16,                       \
                 (const uint4*)g_Wtfl + src_);                                \
        }                                                                     \
        asm volatile("cp.async.commit_group;" ::: "memory");                  \
    } while (0)

    FX_FILL(0);
    for (int hf = 0; hf < 16; hf++) {
        int buf = hf & 1;
        if (hf + 1 < 16) {
            FX_FILL(hf + 1);
            asm volatile("cp.async.wait_group 1;" ::: "memory");
        } else {
            asm volatile("cp.async.wait_group 0;" ::: "memory");
        }
        __syncthreads();    // fill(hf) visible

        const uint2* sWn2h = (const uint2*)(sm + 16384 + buf * 4096);
        const uint2* sWn2l = (const uint2*)(sm + 18432 + buf * 4096);
        const uint2* sWt2h = (const uint2*)(sm + 24576 + buf * 4096);
        const uint2* sWt2l = (const uint2*)(sm + 26624 + buf * 4096);
        uint32_t* sXh = sm + 32768;
        uint32_t* sXl = sm + 34816;

        // ---- nn phase: 128 rows x 8 n per warp (ntile = wc) ----
        float xa[2][4];
#pragma unroll
        for (int mt = 0; mt < 2; mt++)
#pragma unroll
            for (int e = 0; e < 4; e++) xa[mt][e] = 0.f;
#pragma unroll
        for (int s = 0; s < 8; s++) {
            uint4 ah[2], al[2];
#pragma unroll
            for (int mt = 0; mt < 2; mt++) {
                uint32_t i4 = (uint32_t)(((wr * 2 + mt) * 8 + s) * 32 + lane);
                ah[mt] = sS4h[i4];
                al[mt] = sS4l[i4];
            }
            uint32_t i2 = (uint32_t)((wc * 8 + s) * 32 + lane);
            uint2 bh = sWn2h[i2];
            uint2 bl = sWn2l[i2];
#pragma unroll
            for (int mt = 0; mt < 2; mt++)
                mma16816(xa[mt], ah[mt], bh);
#pragma unroll
            for (int mt = 0; mt < 2; mt++)
                mma16816(xa[mt], ah[mt], bl);
#pragma unroll
            for (int mt = 0; mt < 2; mt++)
                mma16816(xa[mt], al[mt], bh);
        }

        // epilogue: relu(x + rn_r) -> X A-frags in smem (+ final out)
        int nb = split * 512 + hf * 32 + wc * 8;     // warp's 8-n base
#pragma unroll
        for (int mt = 0; mt < 2; mt++) {
            int rowg = r0 + wr * 32 + mt * 16 + g;
            float2 rv0 = *(const float2*)(rn + (size_t)rowg * (2 * NDIM)
                                          + nb + 2 * q);
            float2 rv1 = *(const float2*)(rn + (size_t)(rowg + 8) * (2 * NDIM)
                                          + nb + 2 * q);
            float c0 = fmaxf(xa[mt][0] + rv0.x, 0.f);
            float c1 = fmaxf(xa[mt][1] + rv0.y, 0.f);
            float c2 = fmaxf(xa[mt][2] + rv1.x, 0.f);
            float c3 = fmaxf(xa[mt][3] + rv1.y, 0.f);
            uint32_t h01, l01, h23, l23;
            split_pack(c0, c1, h01, l01);
            split_pack(c2, c3, h23, l23);
            // A-frag slot: ktile = wc>>1, reg pair = (wc&1)*2
            uint32_t xi = (uint32_t)(((wr * 2 + mt) * 2 + (wc >> 1)) * 128
                                     + lane * 4 + (wc & 1) * 2);
            sXh[xi] = h01; sXh[xi + 1] = h23;
            sXl[xi] = l01; sXl[xi + 1] = l23;
            if (final_out) {
                size_t b0 = (size_t)rowg * (2 * NDIM);
                size_t b1 = (size_t)(rowg + 8) * (2 * NDIM);
                *(float2*)(outx + b0 + nb + 2 * q) = make_float2(c0, c1);
                *(float2*)(outx + b1 + nb + 2 * q) = make_float2(c2, c3);
                *(float2*)(outx + b0 + NDIM + nb + 2 * q) = make_float2(0.f, 0.f);
                *(float2*)(outx + b1 + NDIM + nb + 2 * q) = make_float2(0.f, 0.f);
            }
        }
        __syncthreads();    // X staging complete

        // ---- nt phase: P += X_slice @ Wt^T (k = 32 n = 2 k16-steps) ----
        const uint4* sX4h = (const uint4*)sXh;
        const uint4* sX4l = (const uint4*)sXl;
#pragma unroll
        for (int s = 0; s < 2; s++) {
            uint4 ah[2], al[2];
#pragma unroll
            for (int mt = 0; mt < 2; mt++) {
                uint32_t i4 = (uint32_t)(((wr * 2 + mt) * 2 + s) * 32 + lane);
                ah[mt] = sX4h[i4];
                al[mt] = sX4l[i4];
            }
#pragma unroll
            for (int ntj = 0; ntj < 4; ntj++) {
                int jtile = wc * 4 + ntj;                    // 0..15
                int jblk = jtile >> 3, jt = jtile & 7;
                uint32_t i2 = (uint32_t)(((jblk * 8 + jt) * 2 + s) * 32 + lane);
                uint2 bh = sWt2h[i2];
                uint2 bl = sWt2l[i2];
#pragma unroll
                for (int mt = 0; mt < 2; mt++) {
                    mma16816(P[mt][ntj], ah[mt], bh);
                    mma16816(P[mt][ntj], ah[mt], bl);
                    mma16816(P[mt][ntj], al[mt], bh);
                }
            }
        }
        __syncthreads();    // done reading buf before fill(hf+2) overwrites
    }
#undef FX_FILL

    float* pb = part + ((size_t)split * BATCH + r0) * TM2;
#pragma unroll
    for (int mt = 0; mt < 2; mt++) {
        int row = wr * 32 + mt * 16 + g;
#pragma unroll
        for (int ntj = 0; ntj < 4; ntj++) {
            int col = wc * 32 + ntj * 8 + 2 * q;
            *(float2*)&pb[(size_t)row * TM2 + col] =
                make_float2(P[mt][ntj][0], P[mt][ntj][1]);
            *(float2*)&pb[(size_t)(row + 8) * TM2 + col] =
                make_float2(P[mt][ntj][2], P[mt][ntj][3]);
        }
    }
}

// ============================================================================
// nt2 (setup only: W W^T and rn projections) — unchanged passing kernel
// ============================================================================
__global__ void __launch_bounds__(256, 2)
nt2(const uint32_t* __restrict__ Afh, const uint32_t* __restrict__ Afl,
    float* __restrict__ part, int rows, int nsubs) {
    extern __shared__ uint32_t sm[];
    uint32_t sb = smem_u32(sm);
    const uint4* sA4h = (const uint4*)sm;
    const uint4* sA4l = (const uint4*)(sm + 8192);
    const uint2* sB2h = (const uint2*)(sm + 16384);
    const uint2* sB2l = (const uint2*)(sm + 20480);
    int tid = threadIdx.x;
    int lane = tid & 31, wid = tid >> 5;
    int wr = wid >> 1, wc = wid & 1;
    int rtile = blockIdx.x;
    int split = blockIdx.y;
    int jblk  = blockIdx.z;
    int r0 = rtile * 128;
    int q = lane & 3, g = lane >> 2;
    int H = nsubs * 2;

    float acc[2][4][4];
#pragma unroll
    for (int mt = 0; mt < 2; mt++)
#pragma unroll
        for (int nt = 0; nt < 4; nt++)
#pragma unroll
            for (int e = 0; e < 4; e++) acc[mt][nt][e] = 0.f;

#define NT2_FILL(h)                                                           \
    do {                                                                      \
        int ksub_ = split * nsubs + ((h) >> 1);                               \
        int s0_ = ((h) & 1) * 4;                                              \
        int buf_ = (h) & 1;                                                   \
        const uint4* gAh4 = (const uint4*)Afh                                 \
                            + ((size_t)rtile * 64 + ksub_) * 2048;            \
        const uint4* gAl4 = (const uint4*)Afl                                 \
                            + ((size_t)rtile * 64 + ksub_) * 2048;            \
        const uint4* gBh4 = (const uint4*)g_Wtfh                              \
                            + ((size_t)ksub_ * 2 + jblk) * 1024;              \
        const uint4* gBl4 = (const uint4*)g_Wtfl                              \
                            + ((size_t)ksub_ * 2 + jblk) * 1024;              \
        _Pragma("unroll")                                                     \
        for (int j_ = 0; j_ < 4; j_++) {                                      \
            int i_ = tid + j_ * 256;                                          \
            int seg_ = i_ >> 5, e_ = i_ & 31;                                 \
            int rg_ = seg_ >> 2, tl_ = seg_ & 3;                              \
            const uint4* sh_ = gAh4 + (rg_ * 8 + s0_ + tl_) * 32 + e_;        \
            const uint4* sl_ = gAl4 + (rg_ * 8 + s0_ + tl_) * 32 + e_;        \
            cp16(sb + buf_ * 16384 + i_ * 16, sh_);                           \
            cp16(sb + 32768 + buf_ * 16384 + i_ * 16, sl_);                   \
        }                                                                     \
        _Pragma("unroll")                                                     \
        for (int j_ = 0; j_ < 2; j_++) {                                      \
            int i_ = tid + j_ * 256;                                          \
            int seg_ = i_ >> 4, e_ = i_ & 15;                                 \
            int ng_ = seg_ >> 2, tl_ = seg_ & 3;                              \
            const uint4* sh_ = gBh4 + (ng_ * 8 + s0_ + tl_) * 16 + e_;        \
            const uint4* sl_ = gBl4 + (ng_ * 8 + s0_ + tl_) * 16 + e_;        \
            cp16(sb + 65536 + buf_ * 8192 + i_ * 16, sh_);                    \
            cp16(sb + 81920 + buf_ * 8192 + i_ * 16, sl_);                    \
        }                                                                     \
        asm volatile("cp.async.commit_group;" ::: "memory");                  \
    } while (0)

    NT2_FILL(0);
    for (int h = 0; h < H; h++) {
        if (h + 1 < H) {
            NT2_FILL(h + 1);
            asm volatile("cp.async.wait_group 1;" ::: "memory");
        } else {
            asm volatile("cp.async.wait_group 0;" ::: "memory");
        }
        __syncthreads();
        int buf = h & 1;
#pragma unroll
        for (int s = 0; s < 4; s++) {
            uint4 ah[2], al[2];
            uint2 bh[4], bl[4];
#pragma unroll
            for (int mt = 0; mt < 2; mt++) {
                uint32_t i4 = (uint32_t)(buf * 1024
                               + ((wr * 2 + mt) * 4 + s) * 32 + lane);
                ah[mt] = sA4h[i4];
                al[mt] = sA4l[i4];
            }
#pragma unroll
            for (int nt = 0; nt < 4; nt++) {
                uint32_t i2 = (uint32_t)(buf * 1024
                               + ((wc * 4 + nt) * 4 + s) * 32 + lane);
                bh[nt] = sB2h[i2];
                bl[nt] = sB2l[i2];
            }
#pragma unroll
            for (int mt = 0; mt < 2; mt++)
#pragma unroll
                for (int nt = 0; nt < 4; nt++)
                    mma16816(acc[mt][nt], ah[mt], bh[nt]);
#pragma unroll
            for (int mt = 0; mt < 2; mt++)
#pragma unroll
                for (int nt = 0; nt < 4; nt++)
                    mma16816(acc[mt][nt], ah[mt], bl[nt]);
#pragma unroll
            for (int mt = 0; mt < 2; mt++)
#pragma unroll
                for (int nt = 0; nt < 4; nt++)
                    mma16816(acc[mt][nt], al[mt], bh[nt]);
        }
        __syncthreads();
    }
#undef NT2_FILL

    float* pb = part + ((size_t)split * rows + r0) * TM2;
#pragma unroll
    for (int mt = 0; mt < 2; mt++) {
        int row = wr * 32 + mt * 16 + g;
#pragma unroll
        for (int nt = 0; nt < 4; nt++) {
            int col = jblk * 64 + wc * 32 + nt * 8 + 2 * q;
            *(float2*)&pb[(size_t)row * TM2 + col] =
                make_float2(acc[mt][nt][0], acc[mt][nt][1]);
            *(float2*)&pb[(size_t)(row + 8) * TM2 + col] =
                make_float2(acc[mt][nt][2], acc[mt][nt][3]);
        }
    }
}

// deterministic fixed-order split reduction (W W^T)
__global__ void reduce_nt(const float4* __restrict__ part,
                          float4* __restrict__ out, int count4, int nsplit) {
    int i = blockIdx.x * 256 + threadIdx.x;
    if (i < count4) {
        float4 s = make_float4(0.f, 0.f, 0.f, 0.f);
        for (int k = 0; k < nsplit; k++) {
            float4 v = part[(size_t)k * count4 + i];
            s.x += v.x; s.y += v.y; s.z += v.z; s.w += v.w;
        }
        out[i] = s;
    }
}

// ---------------- fp32 -> A-fragment conversion (smem-staged) ---------------
__global__ void to_afrag(const float* __restrict__ src,
                         uint32_t* __restrict__ dfh,
                         uint32_t* __restrict__ dfl) {
    extern __shared__ uint32_t sm[];
    uint32_t* sh = sm;
    uint32_t* sl = sm + 8192;
    int tid = threadIdx.x;
    int rtile = blockIdx.x, ksub = blockIdx.y;
#pragma unroll
    for (int i = 0; i < 32; i++) {
        int idx = tid + i * 256;
        int rowl = idx >> 6, kpl = idx & 63;
        float2 v = *(const float2*)(src
                    + (size_t)(rtile * 128 + rowl) * NDIM + ksub * 128 + 2 * kpl);
        uint32_t ad = a_addr(rowl, kpl);
        uint32_t h, l;
        split_pack(v.x, v.y, h, l);
        sh[ad] = h;
        sl[ad] = l;
    }
    __syncthreads();
    size_t base = ((size_t)rtile * 64 + ksub) * 2048;
#pragma unroll
    for (int i = 0; i < 8; i++) {
        ((uint4*)dfh)[base + tid + i * 256] = ((const uint4*)sh)[tid + i * 256];
        ((uint4*)dfl)[base + tid + i * 256] = ((const uint4*)sl)[tid + i * 256];
    }
}

// ---------------- W B-fragment precomputes ----------------------------------
__global__ void wf_nn(const float* __restrict__ W) {
    int idx = blockIdx.x * 256 + threadIdx.x;
    if (idx < 8192 * 64) {
        int n = idx >> 6, kp = idx & 63;
        float v0 = W[(size_t)(2 * kp) * NDIM + n];
        float v1 = W[(size_t)(2 * kp + 1) * NDIM + n];
        int nblk = n >> 6, nl = n & 63;
        uint32_t ad = (uint32_t)nblk * 4096 + b_addr(nl, kp);
        uint32_t h, l;
        split_pack(v0, v1, h, l);
        g_Wnfh[ad] = h;
        g_Wnfl[ad] = l;
    }
}
__global__ void wf_nt(const float* __restrict__ W) {
    int idx = blockIdx.x * 256 + threadIdx.x;
    if (idx < 128 * 4096) {
        int j = idx >> 12, k2 = idx & 4095;
        float v0 = W[(size_t)j * NDIM + 2 * k2];
        float v1 = W[(size_t)j * NDIM + 2 * k2 + 1];
        int ksub = k2 >> 6, kpl = k2 & 63;
        int jblk = j >> 6, jl = j & 63;
        uint32_t ad = (uint32_t)(ksub * 2 + jblk) * 4096 + b_addr(jl, kpl);
        uint32_t h, l;
        split_pack(v0, v1, h, l);
        g_Wtfh[ad] = h;
        g_Wtfl[ad] = l;
    }
}

// ---------------- build G and S = G + I/rho ---------------------------------
__global__ void build_S(const float* __restrict__ log_rho) {
    int idx = blockIdx.x * blockDim.x + threadIdx.x;
    float inv_rho = 1.f / (expf(log_rho[0]) + 1e-12f);
    int p = idx >> 7, q = idx & 127;
    float sgn = ((p < 64) == (q < 64)) ? 1.f : -1.f;
    float g = g_M[idx] + sgn * g_M[((p ^ 64) << 7) + (q ^ 64)];
    g_G[idx] = g;
    g_S[idx] = g + ((p == q) ? inv_rho : 0.f);
}

// ---------------- Newton-Schulz inverse -------------------------------------
__global__ void gersh_initX1() {
    __shared__ float smax[4], smin[4], s_x0;
    int i = threadIdx.x;
    float rs = 0.f, dg = 0.f;
#pragma unroll 8
    for (int k = 0; k < 128; k++) {
        float v = g_S[i * 128 + k];
        rs += fabsf(v);
        if (k == i) dg = v;
    }
    float lo = 2.f * dg - rs;
    float mx = rs, mn = lo;
#pragma unroll
    for (int o = 16; o > 0; o >>= 1) {
        mx = fmaxf(mx, __shfl_down_sync(0xffffffffu, mx, o));
        mn = fminf(mn, __shfl_down_sync(0xffffffffu, mn, o));
    }
    if ((i & 31) == 0) { smax[i >> 5] = mx; smin[i >> 5] = mn; }
    __syncthreads();
    if (i == 0) {
        float lmax = fmaxf(fmaxf(smax[0], smax[1]), fmaxf(smax[2], smax[3]));
        float lmin = fminf(fminf(smin[0], smin[1]), fminf(smin[2], smin[3]));
        s_x0 = (lmin > 0.f) ? 2.f / (lmax + lmin) : 1.f / lmax;
    }
    __syncthreads();
    float x0 = s_x0;
    for (int e = i; e < 128 * 128; e += 128) {
        int p = e >> 7, q = e & 127;
        g_NSa[e] = 2.f * x0 * ((p == q) ? 1.f : 0.f) - x0 * x0 * g_S[e];
    }
}
__global__ void __launch_bounds__(256)
ns_step(const float* __restrict__ X, float* __restrict__ Xn) {
    __shared__ float xr[2][128];
    __shared__ float t[2][128];
    int tid = threadIdx.x;
    int r0 = blockIdx.x * 2;
    int rr = tid >> 7, j = tid & 127;
    xr[rr][j] = X[(r0 + rr) * 128 + j];
    __syncthreads();
    float acc = 0.f;
#pragma unroll 8
    for (int k = 0; k < 128; k++)
        acc = fmaf(xr[rr][k], g_S[k * 128 + j], acc);
    t[rr][j] = acc;
    __syncthreads();
    float acc2 = 0.f;
#pragma unroll 8
    for (int k = 0; k < 128; k++)
        acc2 = fmaf(t[rr][k], X[k * 128 + j], acc2);
    Xn[(r0 + rr) * 128 + j] = 2.f * xr[rr][j] - acc2;
}

// fused: blocks 0-127 -> HT rows; blocks 128-255 -> d = Sinv @ c
__global__ void HT_d(const float* __restrict__ Sinv,
                     const float* __restrict__ log_rho) {
    int tid = threadIdx.x;
    if (blockIdx.x < 128) {
        __shared__ float gk[128];
        int j = tid, k = blockIdx.x;
        float rho = expf(log_rho[0]);
        gk[j] = g_G[k * 128 + j];
        __syncthreads();
        float acc = 0.f;
#pragma unroll 4
        for (int m = 0; m < 128; m++)
            acc = fmaf(Sinv[m * 128 + j], gk[m], acc);
        g_HT[k * 128 + j] = rho * (((j == k) ? 1.f : 0.f) - acc);
    } else {
        __shared__ float cb[8][128];
        int b0 = (blockIdx.x - 128) * 8;
#pragma unroll
        for (int bb = 0; bb < 8; bb++) {
            int b = b0 + bb;
            float pa = 0.f, pbv = 0.f;
#pragma unroll
            for (int sp = 0; sp < 8; sp++) {
                pa  += g_part[((size_t)sp * 2048 + 2 * b) * TM2 + tid];
                pbv += g_part[((size_t)sp * 2048 + 2 * b + 1) * TM2 + (tid ^ 64)];
            }
            cb[bb][tid] = (tid < 64) ? pa - pbv : pa + pbv;
        }
        __syncthreads();
        float acc[8];
#pragma unroll
        for (int bb = 0; bb < 8; bb++) acc[bb] = 0.f;
        for (int k = 0; k < 128; k++) {
            float sv = Sinv[k * 128 + tid];
#pragma unroll
            for (int bb = 0; bb < 8; bb++) acc[bb] = fmaf(sv, cb[bb][k], acc[bb]);
        }
#pragma unroll
        for (int bb = 0; bb < 8; bb++)
            g_d[(b0 + bb) * TM2 + tid] = acc[bb];
    }
}

// s for iter 0: w = y - u_in; s = H w - d (frag output); init g_u
__global__ void s_init(const float* __restrict__ y,
                       const float* __restrict__ u_in) {
    __shared__ float w[8][128];
    int tid = threadIdx.x;
    int b0 = blockIdx.x * 8;
#pragma unroll
    for (int bb = 0; bb < 8; bb++) {
        float uv = u_in[(b0 + bb) * TM2 + tid];
        g_u[(b0 + bb) * TM2 + tid] = uv;
        w[bb][tid] = y[(b0 + bb) * TM2 + tid] - uv;
    }
    __syncthreads();
    float acc[8];
#pragma unroll
    for (int bb = 0; bb < 8; bb++) acc[bb] = 0.f;
    for (int k = 0; k < 128; k++) {
        float h = g_HT[k * 128 + tid];
#pragma unroll
        for (int bb = 0; bb < 8; bb++) acc[bb] = fmaf(h, w[bb][k], acc[bb]);
    }
    __syncthreads();
#pragma unroll
    for (int bb = 0; bb < 8; bb++)
        w[bb][tid] = acc[bb] - g_d[(b0 + bb) * TM2 + tid];
    __syncthreads();
    if (tid < 64) {
#pragma unroll
        for (int bb = 0; bb < 8; bb++) {
            int b = b0 + bb;
            int row = b & 127, rtile = b >> 7, kp = tid;
            uint32_t h, l;
            split_pack(w[bb][2 * kp], w[bb][2 * kp + 1], h, l);
            uint32_t ad = (uint32_t)rtile * 8192 + a_addr(row, kp);
            g_sfh[ad] = h;
            g_sfl[ad] = l;
        }
    }
}

// fused: P = reduce(partials); zu update; s(frag) for next iter / final u out
__global__ void zus(const float* __restrict__ y,
                    const float* __restrict__ log_eps, int compute_s,
                    float* __restrict__ uout) {
    __shared__ float red[4];
    __shared__ float w[128];
    int b = blockIdx.x;
    int j = threadIdx.x;
    float eps = expf(log_eps[0]);
    float Pv = 0.f;
#pragma unroll
    for (int ks = 0; ks < NSPLIT; ks++)
        Pv += g_part[((size_t)ks * BATCH + b) * TM2 + j];
    float uv = g_u[b * TM2 + j];
    float yv = y[b * TM2 + j];
    float v = Pv + uv - yv;
    float t = v * v;
#pragma unroll
    for (int o = 16; o > 0; o >>= 1) t += __shfl_down_sync(0xffffffffu, t, o);
    if ((j & 31) == 0) red[j >> 5] = t;
    __syncthreads();
    float nrm = sqrtf(red[0] + red[1] + red[2] + red[3]);
    float scale = fminf(1.f, eps / (nrm + 1e-12f));
    float zv = yv + v * scale;
    float un = uv + Pv - zv;
    if (compute_s) {
        g_u[b * TM2 + j] = un;
        w[j] = zv - un;
        __syncthreads();
        float acc = 0.f;
#pragma unroll 4
        for (int k = 0; k < 128; k++)
            acc = fmaf(g_HT[k * 128 + j], w[k], acc);
        float sval = acc - g_d[b * TM2 + j];
        __syncthreads();
        w[j] = sval;
        __syncthreads();
        if (j < 64) {
            int row = b & 127, rtile = b >> 7, kp = j;
            uint32_t h, l;
            split_pack(w[2 * kp], w[2 * kp + 1], h, l);
            uint32_t ad = (uint32_t)rtile * 8192 + a_addr(row, kp);
            g_sfh[ad] = h;
            g_sfl[ad] = l;
        }
    } else {
        uout[(size_t)BATCH * 2 * NDIM + b * TM2 + j] = un;
    }
}

// ---------------- launch ----------------------------------------------------
extern "C" void kernel_launch(void* const* d_in, const int* in_sizes, int n_in,
                              void* d_out, int out_size) {
    const float* rn   = (const float*)d_in[0];
    const float* y    = (const float*)d_in[1];
    const float* u_in = (const float*)d_in[2];
    const float* A    = (const float*)d_in[3];
    const float* lrho = (const float*)d_in[4];
    const float* leps = (const float*)d_in[5];
    float* out = (float*)d_out;
    (void)in_sizes; (void)n_in; (void)out_size;

    float *dM, *dPart, *dNSa, *dNSb;
    uint32_t *dWafh, *dWafl, *drnfh, *drnfl;
    cudaGetSymbolAddress((void**)&dM,    g_M);
    cudaGetSymbolAddress((void**)&dPart, g_part);
    cudaGetSymbolAddress((void**)&dNSa,  g_NSa);
    cudaGetSymbolAddress((void**)&dNSb,  g_NSb);
    cudaGetSymbolAddress((void**)&dWafh, g_Wafh);
    cudaGetSymbolAddress((void**)&dWafl, g_Wafl);
    cudaGetSymbolAddress((void**)&drnfh, g_rnfh);
    cudaGetSymbolAddress((void**)&drnfl, g_rnfl);

    static int attr_set = 0;
    if (!attr_set) {
        cudaFuncSetAttribute(nt2, cudaFuncAttributeMaxDynamicSharedMemorySize,
                             NT_SMEM_BYTES);
        cudaFuncSetAttribute(fused_xp,
                             cudaFuncAttributeMaxDynamicSharedMemorySize,
                             FX_SMEM_BYTES);
        cudaFuncSetAttribute(to_afrag,
                             cudaFuncAttributeMaxDynamicSharedMemorySize,
                             AF_SMEM_BYTES);
        attr_set = 1;
    }

    // W fragment layouts + A-frag conversions
    wf_nn<<<(8192 * 64 + 255) / 256, 256>>>(A);
    wf_nt<<<(128 * 4096 + 255) / 256, 256>>>(A);
    to_afrag<<<dim3(1, 64), 256, AF_SMEM_BYTES>>>(A, dWafh, dWafl);
    to_afrag<<<dim3(16, 64), 256, AF_SMEM_BYTES>>>(rn, drnfh, drnfl);

    // M = W W^T (32-way split), then S
    nt2<<<dim3(1, 32, 2), 256, NT_SMEM_BYTES>>>(dWafh, dWafl, dPart, 128, 2);
    reduce_nt<<<(4096 + 255) / 256, 256>>>((const float4*)dPart,
                                           (float4*)dM, 4096, 32);
    build_S<<<64, 256>>>(lrho);

    // Newton-Schulz inverse: X1 + 3 fused steps
    gersh_initX1<<<1, 128>>>();
    ns_step<<<64, 256>>>(dNSa, dNSb);
    ns_step<<<64, 256>>>(dNSb, dNSa);
    ns_step<<<64, 256>>>(dNSa, dNSb);
    const float* Sinv = dNSb;

    // rn projections (2048 rows, 8-way split), fused HT + d, then s iter 0
    nt2<<<dim3(16, 8, 2), 256, NT_SMEM_BYTES>>>(drnfh, drnfl, dPart, 2048, 8);
    HT_d<<<256, 128>>>(Sinv, lrho);
    s_init<<<128, 128>>>(y, u_in);

    for (int it = 0; it < 3; it++) {
        int fin = (it == 2);
        fused_xp<<<dim3(16, 8), 512, FX_SMEM_BYTES>>>(rn, out, fin, dPart);
        zus<<<BATCH, 128>>>(y, leps, it < 2, out);
    }
}

// round 16
// speedup vs baseline: 1.1486x; 1.0788x over previous
#include <cuda_runtime.h>
#include <cuda_bf16.h>
#include <math.h>
#include <stdint.h>

#define BATCH 1024
#define NDIM  8192
#define TM2   128
#define NSPLIT 18                 // fused loop splits (uneven: 4x15 + 14x14 slices)

#define NT_SMEM_BYTES 98304
#define AF_SMEM_BYTES 65536
#define FX_SMEM_BYTES 147456      // fused kernel: 144KB
#define PR_SMEM_BYTES 131072      // projection kernel: 128KB

// ---------------- scratch (static device globals; no runtime alloc) --------
__device__ float g_part[(size_t)18 * 1024 * TM2];    // covers all users
__device__ float g_d [BATCH * TM2];
__device__ float g_u [BATCH * TM2];
__device__ float g_M   [TM2 * TM2];
__device__ float g_G   [TM2 * TM2];
__device__ float g_S   [TM2 * TM2];
__device__ float g_NSa [TM2 * TM2];
__device__ float g_NSb [TM2 * TM2];
__device__ float g_HT  [TM2 * TM2];
__device__ uint32_t g_sfh[8 * 8192];                 // s A-frags [rtile][8192]
__device__ uint32_t g_sfl[8 * 8192];
__device__ uint32_t g_Wafh[64 * 8192];               // W A-frags [ksub]
__device__ uint32_t g_Wafl[64 * 8192];
__device__ uint32_t g_Wnfh[128 * 4096];              // nn B-frags (n-hierarchical)
__device__ uint32_t g_Wnfl[128 * 4096];
__device__ uint32_t g_Wtfh[64 * 2 * 4096];           // nt B-frags [ksub][jblk]
__device__ uint32_t g_Wtfl[64 * 2 * 4096];

// ---------------- helpers ----------------------------------------------------
__device__ __forceinline__ uint32_t pack_bf16x2(float a, float b) {
    uint32_t lo = (uint32_t)__bfloat16_as_ushort(__float2bfloat16(a));
    uint32_t hi = (uint32_t)__bfloat16_as_ushort(__float2bfloat16(b));
    return lo | (hi << 16);
}
__device__ __forceinline__ void split_pack(float a, float b,
                                           uint32_t& hi, uint32_t& lo) {
    float ha = __bfloat162float(__float2bfloat16(a));
    float hb = __bfloat162float(__float2bfloat16(b));
    hi = pack_bf16x2(a, b);
    lo = pack_bf16x2(a - ha, b - hb);
}
__device__ __forceinline__ void mma16816(float* c, const uint4& a,
                                         const uint2& b) {
    asm("mma.sync.aligned.m16n8k16.row.col.f32.bf16.bf16.f32 "
        "{%0,%1,%2,%3}, {%4,%5,%6,%7}, {%8,%9}, {%0,%1,%2,%3};"
        : "+f"(c[0]), "+f"(c[1]), "+f"(c[2]), "+f"(c[3])
        : "r"(a.x), "r"(a.y), "r"(a.z), "r"(a.w), "r"(b.x), "r"(b.y));
}
__device__ __forceinline__ uint32_t a_addr(int row, int kp) {
    uint32_t tile = (uint32_t)((row >> 4) * 8 + (kp >> 3));
    uint32_t lane = ((row & 7) << 2) + (kp & 3);
    uint32_t reg = ((row >> 3) & 1) | (((kp >> 2) & 1) << 1);
    return tile * 128 + lane * 4 + reg;
}
__device__ __forceinline__ uint32_t b_addr(int n, int kp) {
    uint32_t tile = (uint32_t)((n >> 3) * 8 + (kp >> 3));
    uint32_t lane = ((n & 7) << 2) + (kp & 3);
    uint32_t reg = (kp >> 2) & 1;
    return tile * 64 + lane * 2 + reg;
}
__device__ __forceinline__ uint32_t smem_u32(const void* p) {
    uint32_t a;
    asm("{ .reg .u64 t; cvta.to.shared.u64 t, %1; cvt.u32.u64 %0, t; }"
        : "=r"(a) : "l"(p));
    return a;
}
__device__ __forceinline__ void cp16(uint32_t saddr, const void* g) {
    asm volatile("cp.async.cg.shared.global [%0], [%1], 16;"
                 :: "r"(saddr), "l"(g));
}

// ============================================================================
// FUSED loop kernel (18 uneven splits, rn prefetch).
// grid (18 splits, 8 rtiles), 512 threads (16 warps: wr=wid>>2, wc=wid&3).
// ============================================================================
__global__ void __launch_bounds__(512, 1)
fused_xp(const float* __restrict__ rn, float* __restrict__ outx,
         int final_out, float* __restrict__ part) {
    extern __shared__ uint32_t sm[];
    uint32_t sb = smem_u32(sm);
    const uint4* sS4h = (const uint4*)sm;                  // 2048 uint4
    const uint4* sS4l = (const uint4*)(sm + 8192);
    int tid = threadIdx.x;
    int lane = tid & 31, wid = tid >> 5;
    int wr = wid >> 2, wc = wid & 3;
    int split = blockIdx.x;        // 0..17
    int rtile = blockIdx.y;        // 0..7
    int lo = split * 14 + (split < 4 ? split : 4);
    int H  = 14 + (split < 4 ? 1 : 0);
    int r0 = rtile * 128;
    int q = lane & 3, g = lane >> 2;

    // persistent s fragment tiles (128 rows x 64 kp, hi/lo)
    {
        const uint4* gh = (const uint4*)g_sfh + (size_t)rtile * 2048;
        const uint4* gl = (const uint4*)g_sfl + (size_t)rtile * 2048;
#pragma unroll
        for (int i = 0; i < 4; i++) {
            ((uint4*)sm)[tid + i * 512] = gh[tid + i * 512];
            ((uint4*)(sm + 8192))[tid + i * 512] = gl[tid + i * 512];
        }
    }

    float P[2][4][4];
#pragma unroll
    for (int mt = 0; mt < 2; mt++)
#pragma unroll
        for (int ntj = 0; ntj < 4; ntj++)
#pragma unroll
            for (int e = 0; e < 4; e++) P[mt][ntj][e] = 0.f;

#define FX_FILL(h)                                                            \
    do {                                                                      \
        int nh_ = lo + (h);                                                   \
        int buf_ = (h) & 1;                                                   \
        const uint4* gnh = (const uint4*)g_Wnfh + (size_t)nh_ * 512;          \
        const uint4* gnl = (const uint4*)g_Wnfl + (size_t)nh_ * 512;          \
        cp16(sb + 65536 + buf_ * 16384 + tid * 16, gnh + tid);                \
        cp16(sb + 73728 + buf_ * 16384 + tid * 16, gnl + tid);                \
        int ksub_ = nh_ >> 2;                                                 \
        int kt0_ = (nh_ & 3) * 2;                                             \
        {                                                                     \
            int jblk_ = tid >> 8;                                             \
            int rem_ = tid & 255;                                             \
            int jt_ = rem_ >> 5, e_ = rem_ & 31;                              \
            size_t src_ = ((size_t)ksub_ * 2 + jblk_) * 1024 + jt_ * 128      \
                          + kt0_ * 16 + e_;                                   \
            cp16(sb + 98304 + buf_ * 16384 + tid * 16,                        \
                 (const uint4*)g_Wtfh + src_);                                \
            cp16(sb + 106496 + buf_ * 16384 + tid * 16,                       \
                 (const uint4*)g_Wtfl + src_);                                \
        }                                                                     \
        asm volatile("cp.async.commit_group;" ::: "memory");                  \
    } while (0)

    FX_FILL(0);
    for (int hf = 0; hf < H; hf++) {
        int buf = hf & 1;
        int nh = lo + hf;
        int nb = nh * 32 + wc * 8;     // warp's 8-n base

        // prefetch rn epilogue values (consumed ~1000 cyc later)
        float2 rv0[2], rv1[2];
#pragma unroll
        for (int mt = 0; mt < 2; mt++) {
            int rowg = r0 + wr * 32 + mt * 16 + g;
            rv0[mt] = *(const float2*)(rn + (size_t)rowg * (2 * NDIM)
                                       + nb + 2 * q);
            rv1[mt] = *(const float2*)(rn + (size_t)(rowg + 8) * (2 * NDIM)
                                       + nb + 2 * q);
        }

        if (hf + 1 < H) {
            FX_FILL(hf + 1);
            asm volatile("cp.async.wait_group 1;" ::: "memory");
        } else {
            asm volatile("cp.async.wait_group 0;" ::: "memory");
        }
        __syncthreads();    // fill(hf) visible

        const uint2* sWn2h = (const uint2*)(sm + 16384 + buf * 4096);
        const uint2* sWn2l = (const uint2*)(sm + 18432 + buf * 4096);
        const uint2* sWt2h = (const uint2*)(sm + 24576 + buf * 4096);
        const uint2* sWt2l = (const uint2*)(sm + 26624 + buf * 4096);
        uint32_t* sXh = sm + 32768;
        uint32_t* sXl = sm + 34816;

        // ---- nn phase ----
        float xa[2][4];
#pragma unroll
        for (int mt = 0; mt < 2; mt++)
#pragma unroll
            for (int e = 0; e < 4; e++) xa[mt][e] = 0.f;
#pragma unroll
        for (int s = 0; s < 8; s++) {
            uint4 ah[2], al[2];
#pragma unroll
            for (int mt = 0; mt < 2; mt++) {
                uint32_t i4 = (uint32_t)(((wr * 2 + mt) * 8 + s) * 32 + lane);
                ah[mt] = sS4h[i4];
                al[mt] = sS4l[i4];
            }
            uint32_t i2 = (uint32_t)((wc * 8 + s) * 32 + lane);
            uint2 bh = sWn2h[i2];
            uint2 bl = sWn2l[i2];
#pragma unroll
            for (int mt = 0; mt < 2; mt++)
                mma16816(xa[mt], ah[mt], bh);
#pragma unroll
            for (int mt = 0; mt < 2; mt++)
                mma16816(xa[mt], ah[mt], bl);
#pragma unroll
            for (int mt = 0; mt < 2; mt++)
                mma16816(xa[mt], al[mt], bh);
        }

        // epilogue: relu(x + rn_r) -> X A-frags in smem (+ final out)
#pragma unroll
        for (int mt = 0; mt < 2; mt++) {
            int rowg = r0 + wr * 32 + mt * 16 + g;
            float c0 = fmaxf(xa[mt][0] + rv0[mt].x, 0.f);
            float c1 = fmaxf(xa[mt][1] + rv0[mt].y, 0.f);
            float c2 = fmaxf(xa[mt][2] + rv1[mt].x, 0.f);
            float c3 = fmaxf(xa[mt][3] + rv1[mt].y, 0.f);
            uint32_t h01, l01, h23, l23;
            split_pack(c0, c1, h01, l01);
            split_pack(c2, c3, h23, l23);
            uint32_t xi = (uint32_t)(((wr * 2 + mt) * 2 + (wc >> 1)) * 128
                                     + lane * 4 + (wc & 1) * 2);
            sXh[xi] = h01; sXh[xi + 1] = h23;
            sXl[xi] = l01; sXl[xi + 1] = l23;
            if (final_out) {
                size_t b0 = (size_t)rowg * (2 * NDIM);
                size_t b1 = (size_t)(rowg + 8) * (2 * NDIM);
                *(float2*)(outx + b0 + nb + 2 * q) = make_float2(c0, c1);
                *(float2*)(outx + b1 + nb + 2 * q) = make_float2(c2, c3);
                *(float2*)(outx + b0 + NDIM + nb + 2 * q) = make_float2(0.f, 0.f);
                *(float2*)(outx + b1 + NDIM + nb + 2 * q) = make_float2(0.f, 0.f);
            }
        }
        __syncthreads();    // X staging complete

        // ---- nt phase: P += X_slice @ Wt^T ----
        const uint4* sX4h = (const uint4*)sXh;
        const uint4* sX4l = (const uint4*)sXl;
#pragma unroll
        for (int s = 0; s < 2; s++) {
            uint4 ah[2], al[2];
#pragma unroll
            for (int mt = 0; mt < 2; mt++) {
                uint32_t i4 = (uint32_t)(((wr * 2 + mt) * 2 + s) * 32 + lane);
                ah[mt] = sX4h[i4];
                al[mt] = sX4l[i4];
            }
#pragma unroll
            for (int ntj = 0; ntj < 4; ntj++) {
                int jtile = wc * 4 + ntj;
                int jblk = jtile >> 3, jt = jtile & 7;
                uint32_t i2 = (uint32_t)(((jblk * 8 + jt) * 2 + s) * 32 + lane);
                uint2 bh = sWt2h[i2];
                uint2 bl = sWt2l[i2];
#pragma unroll
                for (int mt = 0; mt < 2; mt++) {
                    mma16816(P[mt][ntj], ah[mt], bh);
                    mma16816(P[mt][ntj], ah[mt], bl);
                    mma16816(P[mt][ntj], al[mt], bh);
                }
            }
        }
        __syncthreads();
    }
#undef FX_FILL

    float* pb = part + ((size_t)split * BATCH + r0) * TM2;
#pragma unroll
    for (int mt = 0; mt < 2; mt++) {
        int row = wr * 32 + mt * 16 + g;
#pragma unroll
        for (int ntj = 0; ntj < 4; ntj++) {
            int col = wc * 32 + ntj * 8 + 2 * q;
            *(float2*)&pb[(size_t)row * TM2 + col] =
                make_float2(P[mt][ntj][0], P[mt][ntj][1]);
            *(float2*)&pb[(size_t)(row + 8) * TM2 + col] =
                make_float2(P[mt][ntj][2], P[mt][ntj][3]);
        }
    }
}

// ============================================================================
// proj_rn: part[split][r][j] = sum_{k in 1024-chunk} rn[r,k] * W[j,k]
// Inline fp32->bf16 split conversion of rn (no fragment materialization).
// grid (16 rtiles, 8 splits), 512 threads, full j=128 per block.
// ============================================================================
__global__ void __launch_bounds__(512, 1)
proj_rn(const float* __restrict__ rn, float* __restrict__ part) {
    extern __shared__ uint32_t sm[];
    uint32_t* sAh = sm;               // 8192 u32
    uint32_t* sAl = sm + 8192;
    uint32_t* sBh = sm + 16384;       // 8192 u32 (both jblks)
    uint32_t* sBl = sm + 24576;
    int tid = threadIdx.x;
    int lane = tid & 31, wid = tid >> 5;
    int wr = wid >> 2, wc = wid & 3;
    int rtile = blockIdx.x;           // 0..15 (2048 rows)
    int split = blockIdx.y;           // 0..7
    int r0 = rtile * 128;
    int q = lane & 3, g = lane >> 2;

    float acc[2][4][4];
#pragma unroll
    for (int mt = 0; mt < 2; mt++)
#pragma unroll
        for (int ntj = 0; ntj < 4; ntj++)
#pragma unroll
            for (int e = 0; e < 4; e++) acc[mt][ntj][e] = 0.f;

    for (int kl = 0; kl < 8; kl++) {
        int ksub = split * 8 + kl;
        __syncthreads();
        // A fill: inline convert rn fp32 -> bf16 hi/lo fragments
#pragma unroll
        for (int i = 0; i < 16; i++) {
            int idx = tid + i * 512;
            int row = idx >> 6, kp = idx & 63;
            float2 v = *(const float2*)(rn + (size_t)(r0 + row) * NDIM
                                        + ksub * 128 + 2 * kp);
            uint32_t h, l;
            split_pack(v.x, v.y, h, l);
            uint32_t ad = a_addr(row, kp);
            sAh[ad] = h;
            sAl[ad] = l;
        }
        // B copy: both jblks of this ksub (contiguous in g_Wtf)
        {
            const uint4* gh = (const uint4*)g_Wtfh + (size_t)ksub * 2048;
            const uint4* gl = (const uint4*)g_Wtfl + (size_t)ksub * 2048;
#pragma unroll
            for (int i = 0; i < 4; i++) {
                ((uint4*)sBh)[tid + i * 512] = gh[tid + i * 512];
                ((uint4*)sBl)[tid + i * 512] = gl[tid + i * 512];
            }
        }
        __syncthreads();

#pragma unroll
        for (int s = 0; s < 8; s++) {
            uint4 ah[2], al[2];
#pragma unroll
            for (int mt = 0; mt < 2; mt++) {
                uint32_t i4 = (uint32_t)(((wr * 2 + mt) * 8 + s) * 32 + lane);
                ah[mt] = ((const uint4*)sAh)[i4];
                al[mt] = ((const uint4*)sAl)[i4];
            }
            uint2 bh[4], bl[4];
#pragma unroll
            for (int ntj = 0; ntj < 4; ntj++) {
                int jtile = wc * 4 + ntj;
                int jblk = jtile >> 3, jt = jtile & 7;
                uint32_t i2 = (uint32_t)(jblk * 2048 + (jt * 8 + s) * 32 + lane);
                bh[ntj] = ((const uint2*)sBh)[i2];
                bl[ntj] = ((const uint2*)sBl)[i2];
            }
#pragma unroll
            for (int mt = 0; mt < 2; mt++)
#pragma unroll
                for (int ntj = 0; ntj < 4; ntj++)
                    mma16816(acc[mt][ntj], ah[mt], bh[ntj]);
#pragma unroll
            for (int mt = 0; mt < 2; mt++)
#pragma unroll
                for (int ntj = 0; ntj < 4; ntj++)
                    mma16816(acc[mt][ntj], ah[mt], bl[ntj]);
#pragma unroll
            for (int mt = 0; mt < 2; mt++)
#pragma unroll
                for (int ntj = 0; ntj < 4; ntj++)
                    mma16816(acc[mt][ntj], al[mt], bh[ntj]);
        }
    }

    float* pb = part + ((size_t)split * 2048 + r0) * TM2;
#pragma unroll
    for (int mt = 0; mt < 2; mt++) {
        int row = wr * 32 + mt * 16 + g;
#pragma unroll
        for (int ntj = 0; ntj < 4; ntj++) {
            int col = (wc * 4 + ntj) * 8 + 2 * q;
            *(float2*)&pb[(size_t)row * TM2 + col] =
                make_float2(acc[mt][ntj][0], acc[mt][ntj][1]);
            *(float2*)&pb[(size_t)(row + 8) * TM2 + col] =
                make_float2(acc[mt][ntj][2], acc[mt][ntj][3]);
        }
    }
}

// ============================================================================
// nt2 (setup only: W W^T) — unchanged passing kernel
// ============================================================================
__global__ void __launch_bounds__(256, 2)
nt2(const uint32_t* __restrict__ Afh, const uint32_t* __restrict__ Afl,
    float* __restrict__ part, int rows, int nsubs) {
    extern __shared__ uint32_t sm[];
    uint32_t sb = smem_u32(sm);
    const uint4* sA4h = (const uint4*)sm;
    const uint4* sA4l = (const uint4*)(sm + 8192);
    const uint2* sB2h = (const uint2*)(sm + 16384);
    const uint2* sB2l = (const uint2*)(sm + 20480);
    int tid = threadIdx.x;
    int lane = tid & 31, wid = tid >> 5;
    int wr = wid >> 1, wc = wid & 1;
    int rtile = blockIdx.x;
    int split = blockIdx.y;
    int jblk  = blockIdx.z;
    int r0 = rtile * 128;
    int q = lane & 3, g = lane >> 2;
    int H = nsubs * 2;

    float acc[2][4][4];
#pragma unroll
    for (int mt = 0; mt < 2; mt++)
#pragma unroll
        for (int nt = 0; nt < 4; nt++)
#pragma unroll
            for (int e = 0; e < 4; e++) acc[mt][nt][e] = 0.f;

#define NT2_FILL(h)                                                           \
    do {                                                                      \
        int ksub_ = split * nsubs + ((h) >> 1);                               \
        int s0_ = ((h) & 1) * 4;                                              \
        int buf_ = (h) & 1;                                                   \
        const uint4* gAh4 = (const uint4*)Afh                                 \
                            + ((size_t)rtile * 64 + ksub_) * 2048;            \
        const uint4* gAl4 = (const uint4*)Afl                                 \
                            + ((size_t)rtile * 64 + ksub_) * 2048;            \
        const uint4* gBh4 = (const uint4*)g_Wtfh                              \
                            + ((size_t)ksub_ * 2 + jblk) * 1024;              \
        const uint4* gBl4 = (const uint4*)g_Wtfl                              \
                            + ((size_t)ksub_ * 2 + jblk) * 1024;              \
        _Pragma("unroll")                                                     \
        for (int j_ = 0; j_ < 4; j_++) {                                      \
            int i_ = tid + j_ * 256;                                          \
            int seg_ = i_ >> 5, e_ = i_ & 31;                                 \
            int rg_ = seg_ >> 2, tl_ = seg_ & 3;                              \
            const uint4* sh_ = gAh4 + (rg_ * 8 + s0_ + tl_) * 32 + e_;        \
            const uint4* sl_ = gAl4 + (rg_ * 8 + s0_ + tl_) * 32 + e_;        \
            cp16(sb + buf_ * 16384 + i_ * 16, sh_);                           \
            cp16(sb + 32768 + buf_ * 16384 + i_ * 16, sl_);                   \
        }                                                                     \
        _Pragma("unroll")                                                     \
        for (int j_ = 0; j_ < 2; j_++) {                                      \
            int i_ = tid + j_ * 256;                                          \
            int seg_ = i_ >> 4, e_ = i_ & 15;                                 \
            int ng_ = seg_ >> 2, tl_ = seg_ & 3;                              \
            const uint4* sh_ = gBh4 + (ng_ * 8 + s0_ + tl_) * 16 + e_;        \
            const uint4* sl_ = gBl4 + (ng_ * 8 + s0_ + tl_) * 16 + e_;        \
            cp16(sb + 65536 + buf_ * 8192 + i_ * 16, sh_);                    \
            cp16(sb + 81920 + buf_ * 8192 + i_ * 16, sl_);                    \
        }                                                                     \
        asm volatile("cp.async.commit_group;" ::: "memory");                  \
    } while (0)

    NT2_FILL(0);
    for (int h = 0; h < H; h++) {
        if (h + 1 < H) {
            NT2_FILL(h + 1);
            asm volatile("cp.async.wait_group 1;" ::: "memory");
        } else {
            asm volatile("cp.async.wait_group 0;" ::: "memory");
        }
        __syncthreads();
        int buf = h & 1;
#pragma unroll
        for (int s = 0; s < 4; s++) {
            uint4 ah[2], al[2];
            uint2 bh[4], bl[4];
#pragma unroll
            for (int mt = 0; mt < 2; mt++) {
                uint32_t i4 = (uint32_t)(buf * 1024
                               + ((wr * 2 + mt) * 4 + s) * 32 + lane);
                ah[mt] = sA4h[i4];
                al[mt] = sA4l[i4];
            }
#pragma unroll
            for (int nt = 0; nt < 4; nt++) {
                uint32_t i2 = (uint32_t)(buf * 1024
                               + ((wc * 4 + nt) * 4 + s) * 32 + lane);
                bh[nt] = sB2h[i2];
                bl[nt] = sB2l[i2];
            }
#pragma unroll
            for (int mt = 0; mt < 2; mt++)
#pragma unroll
                for (int nt = 0; nt < 4; nt++)
                    mma16816(acc[mt][nt], ah[mt], bh[nt]);
#pragma unroll
            for (int mt = 0; mt < 2; mt++)
#pragma unroll
                for (int nt = 0; nt < 4; nt++)
                    mma16816(acc[mt][nt], ah[mt], bl[nt]);
#pragma unroll
            for (int mt = 0; mt < 2; mt++)
#pragma unroll
                for (int nt = 0; nt < 4; nt++)
                    mma16816(acc[mt][nt], al[mt], bh[nt]);
        }
        __syncthreads();
    }
#undef NT2_FILL

    float* pb = part + ((size_t)split * rows + r0) * TM2;
#pragma unroll
    for (int mt = 0; mt < 2; mt++) {
        int row = wr * 32 + mt * 16 + g;
#pragma unroll
        for (int nt = 0; nt < 4; nt++) {
            int col = jblk * 64 + wc * 32 + nt * 8 + 2 * q;
            *(float2*)&pb[(size_t)row * TM2 + col] =
                make_float2(acc[mt][nt][0], acc[mt][nt][1]);
            *(float2*)&pb[(size_t)(row + 8) * TM2 + col] =
                make_float2(acc[mt][nt][2], acc[mt][nt][3]);
        }
    }
}

// deterministic fixed-order split reduction (W W^T)
__global__ void reduce_nt(const float4* __restrict__ part,
                          float4* __restrict__ out, int count4, int nsplit) {
    int i = blockIdx.x * 256 + threadIdx.x;
    if (i < count4) {
        float4 s = make_float4(0.f, 0.f, 0.f, 0.f);
        for (int k = 0; k < nsplit; k++) {
            float4 v = part[(size_t)k * count4 + i];
            s.x += v.x; s.y += v.y; s.z += v.z; s.w += v.w;
        }
        out[i] = s;
    }
}

// ---------------- fp32 -> A-fragment conversion (W only) --------------------
__global__ void to_afrag(const float* __restrict__ src,
                         uint32_t* __restrict__ dfh,
                         uint32_t* __restrict__ dfl) {
    extern __shared__ uint32_t sm[];
    uint32_t* sh = sm;
    uint32_t* sl = sm + 8192;
    int tid = threadIdx.x;
    int rtile = blockIdx.x, ksub = blockIdx.y;
#pragma unroll
    for (int i = 0; i < 32; i++) {
        int idx = tid + i * 256;
        int rowl = idx >> 6, kpl = idx & 63;
        float2 v = *(const float2*)(src
                    + (size_t)(rtile * 128 + rowl) * NDIM + ksub * 128 + 2 * kpl);
        uint32_t ad = a_addr(rowl, kpl);
        uint32_t h, l;
        split_pack(v.x, v.y, h, l);
        sh[ad] = h;
        sl[ad] = l;
    }
    __syncthreads();
    size_t base = ((size_t)rtile * 64 + ksub) * 2048;
#pragma unroll
    for (int i = 0; i < 8; i++) {
        ((uint4*)dfh)[base + tid + i * 256] = ((const uint4*)sh)[tid + i * 256];
        ((uint4*)dfl)[base + tid + i * 256] = ((const uint4*)sl)[tid + i * 256];
    }
}

// ---------------- W B-fragment precomputes ----------------------------------
__global__ void wf_nn(const float* __restrict__ W) {
    int idx = blockIdx.x * 256 + threadIdx.x;
    if (idx < 8192 * 64) {
        int n = idx >> 6, kp = idx & 63;
        float v0 = W[(size_t)(2 * kp) * NDIM + n];
        float v1 = W[(size_t)(2 * kp + 1) * NDIM + n];
        int nblk = n >> 6, nl = n & 63;
        uint32_t ad = (uint32_t)nblk * 4096 + b_addr(nl, kp);
        uint32_t h, l;
        split_pack(v0, v1, h, l);
        g_Wnfh[ad] = h;
        g_Wnfl[ad] = l;
    }
}
__global__ void wf_nt(const float* __restrict__ W) {
    int idx = blockIdx.x * 256 + threadIdx.x;
    if (idx < 128 * 4096) {
        int j = idx >> 12, k2 = idx & 4095;
        float v0 = W[(size_t)j * NDIM + 2 * k2];
        float v1 = W[(size_t)j * NDIM + 2 * k2 + 1];
        int ksub = k2 >> 6, kpl = k2 & 63;
        int jblk = j >> 6, jl = j & 63;
        uint32_t ad = (uint32_t)(ksub * 2 + jblk) * 4096 + b_addr(jl, kpl);
        uint32_t h, l;
        split_pack(v0, v1, h, l);
        g_Wtfh[ad] = h;
        g_Wtfl[ad] = l;
    }
}

// ---------------- build G and S = G + I/rho ---------------------------------
__global__ void build_S(const float* __restrict__ log_rho) {
    int idx = blockIdx.x * blockDim.x + threadIdx.x;
    float inv_rho = 1.f / (expf(log_rho[0]) + 1e-12f);
    int p = idx >> 7, q = idx & 127;
    float sgn = ((p < 64) == (q < 64)) ? 1.f : -1.f;
    float g = g_M[idx] + sgn * g_M[((p ^ 64) << 7) + (q ^ 64)];
    g_G[idx] = g;
    g_S[idx] = g + ((p == q) ? inv_rho : 0.f);
}

// ---------------- Newton-Schulz inverse -------------------------------------
__global__ void gersh_initX1() {
    __shared__ float smax[4], smin[4], s_x0;
    int i = threadIdx.x;
    float rs = 0.f, dg = 0.f;
#pragma unroll 8
    for (int k = 0; k < 128; k++) {
        float v = g_S[i * 128 + k];
        rs += fabsf(v);
        if (k == i) dg = v;
    }
    float lo = 2.f * dg - rs;
    float mx = rs, mn = lo;
#pragma unroll
    for (int o = 16; o > 0; o >>= 1) {
        mx = fmaxf(mx, __shfl_down_sync(0xffffffffu, mx, o));
        mn = fminf(mn, __shfl_down_sync(0xffffffffu, mn, o));
    }
    if ((i & 31) == 0) { smax[i >> 5] = mx; smin[i >> 5] = mn; }
    __syncthreads();
    if (i == 0) {
        float lmax = fmaxf(fmaxf(smax[0], smax[1]), fmaxf(smax[2], smax[3]));
        float lmin = fminf(fminf(smin[0], smin[1]), fminf(smin[2], smin[3]));
        s_x0 = (lmin > 0.f) ? 2.f / (lmax + lmin) : 1.f / lmax;
    }
    __syncthreads();
    float x0 = s_x0;
    for (int e = i; e < 128 * 128; e += 128) {
        int p = e >> 7, q = e & 127;
        g_NSa[e] = 2.f * x0 * ((p == q) ? 1.f : 0.f) - x0 * x0 * g_S[e];
    }
}
__global__ void __launch_bounds__(256)
ns_step(const float* __restrict__ X, float* __restrict__ Xn) {
    __shared__ float xr[2][128];
    __shared__ float t[2][128];
    int tid = threadIdx.x;
    int r0 = blockIdx.x * 2;
    int rr = tid >> 7, j = tid & 127;
    xr[rr][j] = X[(r0 + rr) * 128 + j];
    __syncthreads();
    float acc = 0.f;
#pragma unroll 8
    for (int k = 0; k < 128; k++)
        acc = fmaf(xr[rr][k], g_S[k * 128 + j], acc);
    t[rr][j] = acc;
    __syncthreads();
    float acc2 = 0.f;
#pragma unroll 8
    for (int k = 0; k < 128; k++)
        acc2 = fmaf(t[rr][k], X[k * 128 + j], acc2);
    Xn[(r0 + rr) * 128 + j] = 2.f * xr[rr][j] - acc2;
}

// fused: blocks 0-127 -> HT rows; blocks 128-255 -> d = Sinv @ c
__global__ void HT_d(const float* __restrict__ Sinv,
                     const float* __restrict__ log_rho) {
    int tid = threadIdx.x;
    if (blockIdx.x < 128) {
        __shared__ float gk[128];
        int j = tid, k = blockIdx.x;
        float rho = expf(log_rho[0]);
        gk[j] = g_G[k * 128 + j];
        __syncthreads();
        float acc = 0.f;
#pragma unroll 4
        for (int m = 0; m < 128; m++)
            acc = fmaf(Sinv[m * 128 + j], gk[m], acc);
        g_HT[k * 128 + j] = rho * (((j == k) ? 1.f : 0.f) - acc);
    } else {
        __shared__ float cb[8][128];
        int b0 = (blockIdx.x - 128) * 8;
#pragma unroll
        for (int bb = 0; bb < 8; bb++) {
            int b = b0 + bb;
            float pa = 0.f, pbv = 0.f;
#pragma unroll
            for (int sp = 0; sp < 8; sp++) {
                pa  += g_part[((size_t)sp * 2048 + 2 * b) * TM2 + tid];
                pbv += g_part[((size_t)sp * 2048 + 2 * b + 1) * TM2 + (tid ^ 64)];
            }
            cb[bb][tid] = (tid < 64) ? pa - pbv : pa + pbv;
        }
        __syncthreads();
        float acc[8];
#pragma unroll
        for (int bb = 0; bb < 8; bb++) acc[bb] = 0.f;
        for (int k = 0; k < 128; k++) {
            float sv = Sinv[k * 128 + tid];
#pragma unroll
            for (int bb = 0; bb < 8; bb++) acc[bb] = fmaf(sv, cb[bb][k], acc[bb]);
        }
#pragma unroll
        for (int bb = 0; bb < 8; bb++)
            g_d[(b0 + bb) * TM2 + tid] = acc[bb];
    }
}

// s for iter 0: w = y - u_in; s = H w - d (frag output); init g_u
__global__ void s_init(const float* __restrict__ y,
                       const float* __restrict__ u_in) {
    __shared__ float w[8][128];
    int tid = threadIdx.x;
    int b0 = blockIdx.x * 8;
#pragma unroll
    for (int bb = 0; bb < 8; bb++) {
        float uv = u_in[(b0 + bb) * TM2 + tid];
        g_u[(b0 + bb) * TM2 + tid] = uv;
        w[bb][tid] = y[(b0 + bb) * TM2 + tid] - uv;
    }
    __syncthreads();
    float acc[8];
#pragma unroll
    for (int bb = 0; bb < 8; bb++) acc[bb] = 0.f;
    for (int k = 0; k < 128; k++) {
        float h = g_HT[k * 128 + tid];
#pragma unroll
        for (int bb = 0; bb < 8; bb++) acc[bb] = fmaf(h, w[bb][k], acc[bb]);
    }
    __syncthreads();
#pragma unroll
    for (int bb = 0; bb < 8; bb++)
        w[bb][tid] = acc[bb] - g_d[(b0 + bb) * TM2 + tid];
    __syncthreads();
    if (tid < 64) {
#pragma unroll
        for (int bb = 0; bb < 8; bb++) {
            int b = b0 + bb;
            int row = b & 127, rtile = b >> 7, kp = tid;
            uint32_t h, l;
            split_pack(w[bb][2 * kp], w[bb][2 * kp + 1], h, l);
            uint32_t ad = (uint32_t)rtile * 8192 + a_addr(row, kp);
            g_sfh[ad] = h;
            g_sfl[ad] = l;
        }
    }
}

// fused: P = reduce(partials); zu update; s(frag) for next iter / final u out
__global__ void zus(const float* __restrict__ y,
                    const float* __restrict__ log_eps, int compute_s,
                    float* __restrict__ uout) {
    __shared__ float red[4];
    __shared__ float w[128];
    int b = blockIdx.x;
    int j = threadIdx.x;
    float eps = expf(log_eps[0]);
    float Pv = 0.f;
#pragma unroll
    for (int ks = 0; ks < NSPLIT; ks++)
        Pv += g_part[((size_t)ks * BATCH + b) * TM2 + j];
    float uv = g_u[b * TM2 + j];
    float yv = y[b * TM2 + j];
    float v = Pv + uv - yv;
    float t = v * v;
#pragma unroll
    for (int o = 16; o > 0; o >>= 1) t += __shfl_down_sync(0xffffffffu, t, o);
    if ((j & 31) == 0) red[j >> 5] = t;
    __syncthreads();
    float nrm = sqrtf(red[0] + red[1] + red[2] + red[3]);
    float scale = fminf(1.f, eps / (nrm + 1e-12f));
    float zv = yv + v * scale;
    float un = uv + Pv - zv;
    if (compute_s) {
        g_u[b * TM2 + j] = un;
        w[j] = zv - un;
        __syncthreads();
        float acc = 0.f;
#pragma unroll 4
        for (int k = 0; k < 128; k++)
            acc = fmaf(g_HT[k * 128 + j], w[k], acc);
        float sval = acc - g_d[b * TM2 + j];
        __syncthreads();
        w[j] = sval;
        __syncthreads();
        if (j < 64) {
            int row = b & 127, rtile = b >> 7, kp = j;
            uint32_t h, l;
            split_pack(w[2 * kp], w[2 * kp + 1], h, l);
            uint32_t ad = (uint32_t)rtile * 8192 + a_addr(row, kp);
            g_sfh[ad] = h;
            g_sfl[ad] = l;
        }
    } else {
        uout[(size_t)BATCH * 2 * NDIM + b * TM2 + j] = un;
    }
}

// ---------------- launch ----------------------------------------------------
extern "C" void kernel_launch(void* const* d_in, const int* in_sizes, int n_in,
                              void* d_out, int out_size) {
    const float* rn   = (const float*)d_in[0];
    const float* y    = (const float*)d_in[1];
    const float* u_in = (const float*)d_in[2];
    const float* A    = (const float*)d_in[3];
    const float* lrho = (const float*)d_in[4];
    const float* leps = (const float*)d_in[5];
    float* out = (float*)d_out;
    (void)in_sizes; (void)n_in; (void)out_size;

    float *dM, *dPart, *dNSa, *dNSb;
    uint32_t *dWafh, *dWafl;
    cudaGetSymbolAddress((void**)&dM,    g_M);
    cudaGetSymbolAddress((void**)&dPart, g_part);
    cudaGetSymbolAddress((void**)&dNSa,  g_NSa);
    cudaGetSymbolAddress((void**)&dNSb,  g_NSb);
    cudaGetSymbolAddress((void**)&dWafh, g_Wafh);
    cudaGetSymbolAddress((void**)&dWafl, g_Wafl);

    static int attr_set = 0;
    if (!attr_set) {
        cudaFuncSetAttribute(nt2, cudaFuncAttributeMaxDynamicSharedMemorySize,
                             NT_SMEM_BYTES);
        cudaFuncSetAttribute(fused_xp,
                             cudaFuncAttributeMaxDynamicSharedMemorySize,
                             FX_SMEM_BYTES);
        cudaFuncSetAttribute(proj_rn,
                             cudaFuncAttributeMaxDynamicSharedMemorySize,
                             PR_SMEM_BYTES);
        cudaFuncSetAttribute(to_afrag,
                             cudaFuncAttributeMaxDynamicSharedMemorySize,
                             AF_SMEM_BYTES);
        attr_set = 1;
    }

    // W fragment layouts + W A-frag conversion
    wf_nn<<<(8192 * 64 + 255) / 256, 256>>>(A);
    wf_nt<<<(128 * 4096 + 255) / 256, 256>>>(A);
    to_afrag<<<dim3(1, 64), 256, AF_SMEM_BYTES>>>(A, dWafh, dWafl);

    // M = W W^T (32-way split), then S
    nt2<<<dim3(1, 32, 2), 256, NT_SMEM_BYTES>>>(dWafh, dWafl, dPart, 128, 2);
    reduce_nt<<<(4096 + 255) / 256, 256>>>((const float4*)dPart,
                                           (float4*)dM, 4096, 32);
    build_S<<<64, 256>>>(lrho);

    // Newton-Schulz inverse: X1 + 3 fused steps
    gersh_initX1<<<1, 128>>>();
    ns_step<<<64, 256>>>(dNSa, dNSb);
    ns_step<<<64, 256>>>(dNSb, dNSa);
    ns_step<<<64, 256>>>(dNSa, dNSb);
    const float* Sinv = dNSb;

    // rn projections (inline convert, 8 splits), fused HT + d, s for iter 0
    proj_rn<<<dim3(16, 8), 512, PR_SMEM_BYTES>>>(rn, dPart);
    HT_d<<<256, 128>>>(Sinv, lrho);
    s_init<<<128, 128>>>(y, u_in);

    for (int it = 0; it < 3; it++) {
        int fin = (it == 2);
        fused_xp<<<dim3(NSPLIT, 8), 512, FX_SMEM_BYTES>>>(rn, out, fin, dPart);
        zus<<<BATCH, 128>>>(y, leps, it < 2, out);
    }
}

// round 17
// speedup vs baseline: 1.1990x; 1.0438x over previous
#include <cuda_runtime.h>
#include <cuda_bf16.h>
#include <math.h>
#include <stdint.h>

#define BATCH 1024
#define NDIM  8192
#define TM2   128
#define NSPLIT 18                 // fused loop splits (2x8 + 16x7 chunks of 64n)

#define NT_SMEM_BYTES 98304
#define AF_SMEM_BYTES 65536
#define FX_SMEM_BYTES 229376      // fused kernel: 224KB
#define PR_SMEM_BYTES 131072      // projection kernel: 128KB

// ---------------- scratch (static device globals; no runtime alloc) --------
__device__ float g_part[(size_t)18 * 1024 * TM2];
__device__ float g_d [BATCH * TM2];
__device__ float g_u [BATCH * TM2];
__device__ float g_M   [TM2 * TM2];
__device__ float g_G   [TM2 * TM2];
__device__ float g_S   [TM2 * TM2];
__device__ float g_NSa [TM2 * TM2];
__device__ float g_NSb [TM2 * TM2];
__device__ float g_HT  [TM2 * TM2];
__device__ uint32_t g_sfh[8 * 8192];                 // s A-frags [rtile][8192]
__device__ uint32_t g_sfl[8 * 8192];
__device__ uint32_t g_Wafh[64 * 8192];               // W A-frags [ksub]
__device__ uint32_t g_Wafl[64 * 8192];
__device__ uint32_t g_Wnfh[128 * 4096];              // nn B-frags [nblk]
__device__ uint32_t g_Wnfl[128 * 4096];
__device__ uint32_t g_Wtfh[64 * 2 * 4096];           // nt B-frags [ksub][jblk]
__device__ uint32_t g_Wtfl[64 * 2 * 4096];

// ---------------- helpers ----------------------------------------------------
__device__ __forceinline__ uint32_t pack_bf16x2(float a, float b) {
    uint32_t lo = (uint32_t)__bfloat16_as_ushort(__float2bfloat16(a));
    uint32_t hi = (uint32_t)__bfloat16_as_ushort(__float2bfloat16(b));
    return lo | (hi << 16);
}
__device__ __forceinline__ void split_pack(float a, float b,
                                           uint32_t& hi, uint32_t& lo) {
    float ha = __bfloat162float(__float2bfloat16(a));
    float hb = __bfloat162float(__float2bfloat16(b));
    hi = pack_bf16x2(a, b);
    lo = pack_bf16x2(a - ha, b - hb);
}
__device__ __forceinline__ void mma16816(float* c, const uint4& a,
                                         const uint2& b) {
    asm("mma.sync.aligned.m16n8k16.row.col.f32.bf16.bf16.f32 "
        "{%0,%1,%2,%3}, {%4,%5,%6,%7}, {%8,%9}, {%0,%1,%2,%3};"
        : "+f"(c[0]), "+f"(c[1]), "+f"(c[2]), "+f"(c[3])
        : "r"(a.x), "r"(a.y), "r"(a.z), "r"(a.w), "r"(b.x), "r"(b.y));
}
__device__ __forceinline__ uint32_t a_addr(int row, int kp) {
    uint32_t tile = (uint32_t)((row >> 4) * 8 + (kp >> 3));
    uint32_t lane = ((row & 7) << 2) + (kp & 3);
    uint32_t reg = ((row >> 3) & 1) | (((kp >> 2) & 1) << 1);
    return tile * 128 + lane * 4 + reg;
}
__device__ __forceinline__ uint32_t b_addr(int n, int kp) {
    uint32_t tile = (uint32_t)((n >> 3) * 8 + (kp >> 3));
    uint32_t lane = ((n & 7) << 2) + (kp & 3);
    uint32_t reg = (kp >> 2) & 1;
    return tile * 64 + lane * 2 + reg;
}
__device__ __forceinline__ uint32_t smem_u32(const void* p) {
    uint32_t a;
    asm("{ .reg .u64 t; cvta.to.shared.u64 t, %1; cvt.u32.u64 %0, t; }"
        : "=r"(a) : "l"(p));
    return a;
}
__device__ __forceinline__ void cp16(uint32_t saddr, const void* g) {
    asm volatile("cp.async.cg.shared.global [%0], [%1], 16;"
                 :: "r"(saddr), "l"(g));
}

// ============================================================================
// FUSED loop kernel: 64-n chunks (2x8 + 16x7 per split).
// grid (18 splits, 8 rtiles), 512 threads (16 warps: wr=wid>>2, wc=wid&3).
// smem (u32): s 0..16383 | Wn 16384+buf*8192 (hi 4096, lo +4096)
//             | Wt 32768+buf*8192 | X hi 49152, lo 53248.  Total 224KB.
// ============================================================================
__global__ void __launch_bounds__(512, 1)
fused_xp(const float* __restrict__ rn, float* __restrict__ outx,
         int final_out, float* __restrict__ part) {
    extern __shared__ uint32_t sm[];
    uint32_t sb = smem_u32(sm);
    const uint4* sS4h = (const uint4*)sm;
    const uint4* sS4l = (const uint4*)(sm + 8192);
    int tid = threadIdx.x;
    int lane = tid & 31, wid = tid >> 5;
    int wr = wid >> 2, wc = wid & 3;
    int split = blockIdx.x;        // 0..17
    int rtile = blockIdx.y;        // 0..7
    int lo = split * 7 + (split < 2 ? split : 2);
    int H  = 7 + (split < 2 ? 1 : 0);
    int r0 = rtile * 128;
    int q = lane & 3, g = lane >> 2;

    // persistent s fragment tiles (128 rows x 64 kp, hi/lo)
    {
        const uint4* gh = (const uint4*)g_sfh + (size_t)rtile * 2048;
        const uint4* gl = (const uint4*)g_sfl + (size_t)rtile * 2048;
#pragma unroll
        for (int i = 0; i < 4; i++) {
            ((uint4*)sm)[tid + i * 512] = gh[tid + i * 512];
            ((uint4*)(sm + 8192))[tid + i * 512] = gl[tid + i * 512];
        }
    }

    float P[2][4][4];
#pragma unroll
    for (int mt = 0; mt < 2; mt++)
#pragma unroll
        for (int ntj = 0; ntj < 4; ntj++)
#pragma unroll
            for (int e = 0; e < 4; e++) P[mt][ntj][e] = 0.f;

    // fill macro: 64-n chunk h into buffer h&1.
#define FX_FILL(h)                                                            \
    do {                                                                      \
        int nh_ = lo + (h);                                                   \
        int buf_ = (h) & 1;                                                   \
        const uint4* gnh = (const uint4*)g_Wnfh + (size_t)nh_ * 1024;         \
        const uint4* gnl = (const uint4*)g_Wnfl + (size_t)nh_ * 1024;         \
        cp16(sb + 65536 + buf_ * 32768 + (tid * 2) * 16, gnh + tid * 2);      \
        cp16(sb + 65536 + buf_ * 32768 + (tid * 2 + 1) * 16,                  \
             gnh + tid * 2 + 1);                                              \
        cp16(sb + 81920 + buf_ * 32768 + (tid * 2) * 16, gnl + tid * 2);      \
        cp16(sb + 81920 + buf_ * 32768 + (tid * 2 + 1) * 16,                  \
             gnl + tid * 2 + 1);                                              \
        int ksub_ = nh_ >> 1;                                                 \
        int kt0_ = (nh_ & 1) * 4;                                             \
        _Pragma("unroll")                                                     \
        for (int j_ = 0; j_ < 2; j_++) {                                      \
            int d_ = tid * 2 + j_;                                            \
            int jblk_ = d_ >> 9;                                              \
            int r_ = d_ & 511;                                                \
            int jt_ = r_ >> 6, s_ = (r_ >> 4) & 3, e_ = r_ & 15;              \
            size_t src_ = ((size_t)ksub_ * 2 + jblk_) * 1024                  \
                          + (jt_ * 8 + kt0_ + s_) * 16 + e_;                  \
            cp16(sb + 131072 + buf_ * 32768 + d_ * 16,                        \
                 (const uint4*)g_Wtfh + src_);                                \
            cp16(sb + 147456 + buf_ * 32768 + d_ * 16,                        \
                 (const uint4*)g_Wtfl + src_);                                \
        }                                                                     \
        asm volatile("cp.async.commit_group;" ::: "memory");                  \
    } while (0)

    FX_FILL(0);
    for (int hf = 0; hf < H; hf++) {
        int buf = hf & 1;
        int nh = lo + hf;
        int nb = nh * 64 + wc * 16;    // warp's 16-n base

        // prefetch rn epilogue values
        float2 rv0[2][2], rv1[2][2];
#pragma unroll
        for (int mt = 0; mt < 2; mt++) {
            int rowg = r0 + wr * 32 + mt * 16 + g;
#pragma unroll
            for (int nt = 0; nt < 2; nt++) {
                int ncol = nb + nt * 8 + 2 * q;
                rv0[mt][nt] = *(const float2*)(rn + (size_t)rowg * (2 * NDIM)
                                               + ncol);
                rv1[mt][nt] = *(const float2*)(rn
                              + (size_t)(rowg + 8) * (2 * NDIM) + ncol);
            }
        }

        if (hf + 1 < H) {
            FX_FILL(hf + 1);
            asm volatile("cp.async.wait_group 1;" ::: "memory");
        } else {
            asm volatile("cp.async.wait_group 0;" ::: "memory");
        }
        __syncthreads();    // fill(hf) visible

        const uint2* sWn2h = (const uint2*)(sm + 16384 + buf * 8192);
        const uint2* sWn2l = (const uint2*)(sm + 20480 + buf * 8192);
        const uint2* sWt2h = (const uint2*)(sm + 32768 + buf * 8192);
        const uint2* sWt2l = (const uint2*)(sm + 36864 + buf * 8192);
        uint32_t* sXh = sm + 49152;
        uint32_t* sXl = sm + 53248;

        // ---- nn phase: 128 rows x 64 n; warp = 32 rows x 16 n ----
        float xa[2][2][4];
#pragma unroll
        for (int mt = 0; mt < 2; mt++)
#pragma unroll
            for (int nt = 0; nt < 2; nt++)
#pragma unroll
                for (int e = 0; e < 4; e++) xa[mt][nt][e] = 0.f;
#pragma unroll
        for (int s = 0; s < 8; s++) {
            uint4 ah[2], al[2];
#pragma unroll
            for (int mt = 0; mt < 2; mt++) {
                uint32_t i4 = (uint32_t)(((wr * 2 + mt) * 8 + s) * 32 + lane);
                ah[mt] = sS4h[i4];
                al[mt] = sS4l[i4];
            }
            uint2 bh[2], bl[2];
#pragma unroll
            for (int nt = 0; nt < 2; nt++) {
                uint32_t i2 = (uint32_t)(((wc * 2 + nt) * 8 + s) * 32 + lane);
                bh[nt] = sWn2h[i2];
                bl[nt] = sWn2l[i2];
            }
#pragma unroll
            for (int mt = 0; mt < 2; mt++)
#pragma unroll
                for (int nt = 0; nt < 2; nt++)
                    mma16816(xa[mt][nt], ah[mt], bh[nt]);
#pragma unroll
            for (int mt = 0; mt < 2; mt++)
#pragma unroll
                for (int nt = 0; nt < 2; nt++)
                    mma16816(xa[mt][nt], ah[mt], bl[nt]);
#pragma unroll
            for (int mt = 0; mt < 2; mt++)
#pragma unroll
                for (int nt = 0; nt < 2; nt++)
                    mma16816(xa[mt][nt], al[mt], bh[nt]);
        }

        // epilogue: relu(x + rn_r) -> X A-frags (4-ktile layout) in smem
#pragma unroll
        for (int mt = 0; mt < 2; mt++) {
            int rowg = r0 + wr * 32 + mt * 16 + g;
#pragma unroll
            for (int nt = 0; nt < 2; nt++) {
                float c0 = fmaxf(xa[mt][nt][0] + rv0[mt][nt].x, 0.f);
                float c1 = fmaxf(xa[mt][nt][1] + rv0[mt][nt].y, 0.f);
                float c2 = fmaxf(xa[mt][nt][2] + rv1[mt][nt].x, 0.f);
                float c3 = fmaxf(xa[mt][nt][3] + rv1[mt][nt].y, 0.f);
                uint32_t h01, l01, h23, l23;
                split_pack(c0, c1, h01, l01);
                split_pack(c2, c3, h23, l23);
                uint32_t xi = (uint32_t)(((wr * 2 + mt) * 4 + wc) * 128
                                         + lane * 4 + nt * 2);
                sXh[xi] = h01; sXh[xi + 1] = h23;
                sXl[xi] = l01; sXl[xi + 1] = l23;
                if (final_out) {
                    int ncol = nb + nt * 8 + 2 * q;
                    size_t b0 = (size_t)rowg * (2 * NDIM);
                    size_t b1 = (size_t)(rowg + 8) * (2 * NDIM);
                    *(float2*)(outx + b0 + ncol) = make_float2(c0, c1);
                    *(float2*)(outx + b1 + ncol) = make_float2(c2, c3);
                    *(float2*)(outx + b0 + NDIM + ncol) = make_float2(0.f, 0.f);
                    *(float2*)(outx + b1 + NDIM + ncol) = make_float2(0.f, 0.f);
                }
            }
        }
        __syncthreads();    // X staging complete

        // ---- nt phase: P += X_chunk @ Wt^T (4 k16-steps) ----
        const uint4* sX4h = (const uint4*)sXh;
        const uint4* sX4l = (const uint4*)sXl;
#pragma unroll
        for (int s = 0; s < 4; s++) {
            uint4 ah[2], al[2];
#pragma unroll
            for (int mt = 0; mt < 2; mt++) {
                uint32_t i4 = (uint32_t)(((wr * 2 + mt) * 4 + s) * 32 + lane);
                ah[mt] = sX4h[i4];
                al[mt] = sX4l[i4];
            }
#pragma unroll
            for (int ntj = 0; ntj < 4; ntj++) {
                int jtile = wc * 4 + ntj;
                int jblk = jtile >> 3, jt = jtile & 7;
                uint32_t i2 = (uint32_t)(((jblk * 8 + jt) * 4 + s) * 32 + lane);
                uint2 bh = sWt2h[i2];
                uint2 bl = sWt2l[i2];
#pragma unroll
                for (int mt = 0; mt < 2; mt++) {
                    mma16816(P[mt][ntj], ah[mt], bh);
                    mma16816(P[mt][ntj], ah[mt], bl);
                    mma16816(P[mt][ntj], al[mt], bh);
                }
            }
        }
        __syncthreads();    // done reading buf before fill(hf+2) overwrites
    }
#undef FX_FILL

    float* pb = part + ((size_t)split * BATCH + r0) * TM2;
#pragma unroll
    for (int mt = 0; mt < 2; mt++) {
        int row = wr * 32 + mt * 16 + g;
#pragma unroll
        for (int ntj = 0; ntj < 4; ntj++) {
            int col = wc * 32 + ntj * 8 + 2 * q;
            *(float2*)&pb[(size_t)row * TM2 + col] =
                make_float2(P[mt][ntj][0], P[mt][ntj][1]);
            *(float2*)&pb[(size_t)(row + 8) * TM2 + col] =
                make_float2(P[mt][ntj][2], P[mt][ntj][3]);
        }
    }
}

// ============================================================================
// proj_rn: part[split][r][j] = sum_{k in 1024-chunk} rn[r,k] * W[j,k]
// ============================================================================
__global__ void __launch_bounds__(512, 1)
proj_rn(const float* __restrict__ rn, float* __restrict__ part) {
    extern __shared__ uint32_t sm[];
    uint32_t* sAh = sm;
    uint32_t* sAl = sm + 8192;
    uint32_t* sBh = sm + 16384;
    uint32_t* sBl = sm + 24576;
    int tid = threadIdx.x;
    int lane = tid & 31, wid = tid >> 5;
    int wr = wid >> 2, wc = wid & 3;
    int rtile = blockIdx.x;
    int split = blockIdx.y;
    int r0 = rtile * 128;
    int q = lane & 3, g = lane >> 2;

    float acc[2][4][4];
#pragma unroll
    for (int mt = 0; mt < 2; mt++)
#pragma unroll
        for (int ntj = 0; ntj < 4; ntj++)
#pragma unroll
            for (int e = 0; e < 4; e++) acc[mt][ntj][e] = 0.f;

    for (int kl = 0; kl < 8; kl++) {
        int ksub = split * 8 + kl;
        __syncthreads();
#pragma unroll
        for (int i = 0; i < 16; i++) {
            int idx = tid + i * 512;
            int row = idx >> 6, kp = idx & 63;
            float2 v = *(const float2*)(rn + (size_t)(r0 + row) * NDIM
                                        + ksub * 128 + 2 * kp);
            uint32_t h, l;
            split_pack(v.x, v.y, h, l);
            uint32_t ad = a_addr(row, kp);
            sAh[ad] = h;
            sAl[ad] = l;
        }
        {
            const uint4* gh = (const uint4*)g_Wtfh + (size_t)ksub * 2048;
            const uint4* gl = (const uint4*)g_Wtfl + (size_t)ksub * 2048;
#pragma unroll
            for (int i = 0; i < 4; i++) {
                ((uint4*)sBh)[tid + i * 512] = gh[tid + i * 512];
                ((uint4*)sBl)[tid + i * 512] = gl[tid + i * 512];
            }
        }
        __syncthreads();

#pragma unroll
        for (int s = 0; s < 8; s++) {
            uint4 ah[2], al[2];
#pragma unroll
            for (int mt = 0; mt < 2; mt++) {
                uint32_t i4 = (uint32_t)(((wr * 2 + mt) * 8 + s) * 32 + lane);
                ah[mt] = ((const uint4*)sAh)[i4];
                al[mt] = ((const uint4*)sAl)[i4];
            }
            uint2 bh[4], bl[4];
#pragma unroll
            for (int ntj = 0; ntj < 4; ntj++) {
                int jtile = wc * 4 + ntj;
                int jblk = jtile >> 3, jt = jtile & 7;
                uint32_t i2 = (uint32_t)(jblk * 2048 + (jt * 8 + s) * 32 + lane);
                bh[ntj] = ((const uint2*)sBh)[i2];
                bl[ntj] = ((const uint2*)sBl)[i2];
            }
#pragma unroll
            for (int mt = 0; mt < 2; mt++)
#pragma unroll
                for (int ntj = 0; ntj < 4; ntj++)
                    mma16816(acc[mt][ntj], ah[mt], bh[ntj]);
#pragma unroll
            for (int mt = 0; mt < 2; mt++)
#pragma unroll
                for (int ntj = 0; ntj < 4; ntj++)
                    mma16816(acc[mt][ntj], ah[mt], bl[ntj]);
#pragma unroll
            for (int mt = 0; mt < 2; mt++)
#pragma unroll
                for (int ntj = 0; ntj < 4; ntj++)
                    mma16816(acc[mt][ntj], al[mt], bh[ntj]);
        }
    }

    float* pb = part + ((size_t)split * 2048 + r0) * TM2;
#pragma unroll
    for (int mt = 0; mt < 2; mt++) {
        int row = wr * 32 + mt * 16 + g;
#pragma unroll
        for (int ntj = 0; ntj < 4; ntj++) {
            int col = (wc * 4 + ntj) * 8 + 2 * q;
            *(float2*)&pb[(size_t)row * TM2 + col] =
                make_float2(acc[mt][ntj][0], acc[mt][ntj][1]);
            *(float2*)&pb[(size_t)(row + 8) * TM2 + col] =
                make_float2(acc[mt][ntj][2], acc[mt][ntj][3]);
        }
    }
}

// ============================================================================
// nt2 (setup only: W W^T)
// ============================================================================
__global__ void __launch_bounds__(256, 2)
nt2(const uint32_t* __restrict__ Afh, const uint32_t* __restrict__ Afl,
    float* __restrict__ part, int rows, int nsubs) {
    extern __shared__ uint32_t sm[];
    uint32_t sb = smem_u32(sm);
    const uint4* sA4h = (const uint4*)sm;
    const uint4* sA4l = (const uint4*)(sm + 8192);
    const uint2* sB2h = (const uint2*)(sm + 16384);
    const uint2* sB2l = (const uint2*)(sm + 20480);
    int tid = threadIdx.x;
    int lane = tid & 31, wid = tid >> 5;
    int wr = wid >> 1, wc = wid & 1;
    int rtile = blockIdx.x;
    int split = blockIdx.y;
    int jblk  = blockIdx.z;
    int r0 = rtile * 128;
    int q = lane & 3, g = lane >> 2;
    int H = nsubs * 2;

    float acc[2][4][4];
#pragma unroll
    for (int mt = 0; mt < 2; mt++)
#pragma unroll
        for (int nt = 0; nt < 4; nt++)
#pragma unroll
            for (int e = 0; e < 4; e++) acc[mt][nt][e] = 0.f;

#define NT2_FILL(h)                                                           \
    do {                                                                      \
        int ksub_ = split * nsubs + ((h) >> 1);                               \
        int s0_ = ((h) & 1) * 4;                                              \
        int buf_ = (h) & 1;                                                   \
        const uint4* gAh4 = (const uint4*)Afh                                 \
                            + ((size_t)rtile * 64 + ksub_) * 2048;            \
        const uint4* gAl4 = (const uint4*)Afl                                 \
                            + ((size_t)rtile * 64 + ksub_) * 2048;            \
        const uint4* gBh4 = (const uint4*)g_Wtfh                              \
                            + ((size_t)ksub_ * 2 + jblk) * 1024;              \
        const uint4* gBl4 = (const uint4*)g_Wtfl                              \
                            + ((size_t)ksub_ * 2 + jblk) * 1024;              \
        _Pragma("unroll")                                                     \
        for (int j_ = 0; j_ < 4; j_++) {                                      \
            int i_ = tid + j_ * 256;                                          \
            int seg_ = i_ >> 5, e_ = i_ & 31;                                 \
            int rg_ = seg_ >> 2, tl_ = seg_ & 3;                              \
            const uint4* sh_ = gAh4 + (rg_ * 8 + s0_ + tl_) * 32 + e_;        \
            const uint4* sl_ = gAl4 + (rg_ * 8 + s0_ + tl_) * 32 + e_;        \
            cp16(sb + buf_ * 16384 + i_ * 16, sh_);                           \
            cp16(sb + 32768 + buf_ * 16384 + i_ * 16, sl_);                   \
        }                                                                     \
        _Pragma("unroll")                                                     \
        for (int j_ = 0; j_ < 2; j_++) {                                      \
            int i_ = tid + j_ * 256;                                          \
            int seg_ = i_ >> 4, e_ = i_ & 15;                                 \
            int ng_ = seg_ >> 2, tl_ = seg_ & 3;                              \
            const uint4* sh_ = gBh4 + (ng_ * 8 + s0_ + tl_) * 16 + e_;        \
            const uint4* sl_ = gBl4 + (ng_ * 8 + s0_ + tl_) * 16 + e_;        \
            cp16(sb + 65536 + buf_ * 8192 + i_ * 16, sh_);                    \
            cp16(sb + 81920 + buf_ * 8192 + i_ * 16, sl_);                    \
        }                                                                     \
        asm volatile("cp.async.commit_group;" ::: "memory");                  \
    } while (0)

    NT2_FILL(0);
    for (int h = 0; h < H; h++) {
        if (h + 1 < H) {
            NT2_FILL(h + 1);
            asm volatile("cp.async.wait_group 1;" ::: "memory");
        } else {
            asm volatile("cp.async.wait_group 0;" ::: "memory");
        }
        __syncthreads();
        int buf = h & 1;
#pragma unroll
        for (int s = 0; s < 4; s++) {
            uint4 ah[2], al[2];
            uint2 bh[4], bl[4];
#pragma unroll
            for (int mt = 0; mt < 2; mt++) {
                uint32_t i4 = (uint32_t)(buf * 1024
                               + ((wr * 2 + mt) * 4 + s) * 32 + lane);
                ah[mt] = sA4h[i4];
                al[mt] = sA4l[i4];
            }
#pragma unroll
            for (int nt = 0; nt < 4; nt++) {
                uint32_t i2 = (uint32_t)(buf * 1024
                               + ((wc * 4 + nt) * 4 + s) * 32 + lane);
                bh[nt] = sB2h[i2];
                bl[nt] = sB2l[i2];
            }
#pragma unroll
            for (int mt = 0; mt < 2; mt++)
#pragma unroll
                for (int nt = 0; nt < 4; nt++)
                    mma16816(acc[mt][nt], ah[mt], bh[nt]);
#pragma unroll
            for (int mt = 0; mt < 2; mt++)
#pragma unroll
                for (int nt = 0; nt < 4; nt++)
                    mma16816(acc[mt][nt], ah[mt], bl[nt]);
#pragma unroll
            for (int mt = 0; mt < 2; mt++)
#pragma unroll
                for (int nt = 0; nt < 4; nt++)
                    mma16816(acc[mt][nt], al[mt], bh[nt]);
        }
        __syncthreads();
    }
#undef NT2_FILL

    float* pb = part + ((size_t)split * rows + r0) * TM2;
#pragma unroll
    for (int mt = 0; mt < 2; mt++) {
        int row = wr * 32 + mt * 16 + g;
#pragma unroll
        for (int nt = 0; nt < 4; nt++) {
            int col = jblk * 64 + wc * 32 + nt * 8 + 2 * q;
            *(float2*)&pb[(size_t)row * TM2 + col] =
                make_float2(acc[mt][nt][0], acc[mt][nt][1]);
            *(float2*)&pb[(size_t)(row + 8) * TM2 + col] =
                make_float2(acc[mt][nt][2], acc[mt][nt][3]);
        }
    }
}

// deterministic fixed-order split reduction (W W^T)
__global__ void reduce_nt(const float4* __restrict__ part,
                          float4* __restrict__ out, int count4, int nsplit) {
    int i = blockIdx.x * 256 + threadIdx.x;
    if (i < count4) {
        float4 s = make_float4(0.f, 0.f, 0.f, 0.f);
        for (int k = 0; k < nsplit; k++) {
            float4 v = part[(size_t)k * count4 + i];
            s.x += v.x; s.y += v.y; s.z += v.z; s.w += v.w;
        }
        out[i] = s;
    }
}

// ---------------- fp32 -> A-fragment conversion (W only) --------------------
__global__ void to_afrag(const float* __restrict__ src,
                         uint32_t* __restrict__ dfh,
                         uint32_t* __restrict__ dfl) {
    extern __shared__ uint32_t sm[];
    uint32_t* sh = sm;
    uint32_t* sl = sm + 8192;
    int tid = threadIdx.x;
    int rtile = blockIdx.x, ksub = blockIdx.y;
#pragma unroll
    for (int i = 0; i < 32; i++) {
        int idx = tid + i * 256;
        int rowl = idx >> 6, kpl = idx & 63;
        float2 v = *(const float2*)(src
                    + (size_t)(rtile * 128 + rowl) * NDIM + ksub * 128 + 2 * kpl);
        uint32_t ad = a_addr(rowl, kpl);
        uint32_t h, l;
        split_pack(v.x, v.y, h, l);
        sh[ad] = h;
        sl[ad] = l;
    }
    __syncthreads();
    size_t base = ((size_t)rtile * 64 + ksub) * 2048;
#pragma unroll
    for (int i = 0; i < 8; i++) {
        ((uint4*)dfh)[base + tid + i * 256] = ((const uint4*)sh)[tid + i * 256];
        ((uint4*)dfl)[base + tid + i * 256] = ((const uint4*)sl)[tid + i * 256];
    }
}

// ---------------- W B-fragment precomputes ----------------------------------
__global__ void wf_nn(const float* __restrict__ W) {
    int idx = blockIdx.x * 256 + threadIdx.x;
    if (idx < 8192 * 64) {
        int n = idx >> 6, kp = idx & 63;
        float v0 = W[(size_t)(2 * kp) * NDIM + n];
        float v1 = W[(size_t)(2 * kp + 1) * NDIM + n];
        int nblk = n >> 6, nl = n & 63;
        uint32_t ad = (uint32_t)nblk * 4096 + b_addr(nl, kp);
        uint32_t h, l;
        split_pack(v0, v1, h, l);
        g_Wnfh[ad] = h;
        g_Wnfl[ad] = l;
    }
}
__global__ void wf_nt(const float* __restrict__ W) {
    int idx = blockIdx.x * 256 + threadIdx.x;
    if (idx < 128 * 4096) {
        int j = idx >> 12, k2 = idx & 4095;
        float v0 = W[(size_t)j * NDIM + 2 * k2];
        float v1 = W[(size_t)j * NDIM + 2 * k2 + 1];
        int ksub = k2 >> 6, kpl = k2 & 63;
        int jblk = j >> 6, jl = j & 63;
        uint32_t ad = (uint32_t)(ksub * 2 + jblk) * 4096 + b_addr(jl, kpl);
        uint32_t h, l;
        split_pack(v0, v1, h, l);
        g_Wtfh[ad] = h;
        g_Wtfl[ad] = l;
    }
}

// ---------------- build G and S = G + I/rho ---------------------------------
__global__ void build_S(const float* __restrict__ log_rho) {
    int idx = blockIdx.x * blockDim.x + threadIdx.x;
    float inv_rho = 1.f / (expf(log_rho[0]) + 1e-12f);
    int p = idx >> 7, q = idx & 127;
    float sgn = ((p < 64) == (q < 64)) ? 1.f : -1.f;
    float g = g_M[idx] + sgn * g_M[((p ^ 64) << 7) + (q ^ 64)];
    g_G[idx] = g;
    g_S[idx] = g + ((p == q) ? inv_rho : 0.f);
}

// ---------------- Newton-Schulz inverse -------------------------------------
__global__ void gersh_initX1() {
    __shared__ float smax[4], smin[4], s_x0;
    int i = threadIdx.x;
    float rs = 0.f, dg = 0.f;
#pragma unroll 8
    for (int k = 0; k < 128; k++) {
        float v = g_S[i * 128 + k];
        rs += fabsf(v);
        if (k == i) dg = v;
    }
    float lo = 2.f * dg - rs;
    float mx = rs, mn = lo;
#pragma unroll
    for (int o = 16; o > 0; o >>= 1) {
        mx = fmaxf(mx, __shfl_down_sync(0xffffffffu, mx, o));
        mn = fminf(mn, __shfl_down_sync(0xffffffffu, mn, o));
    }
    if ((i & 31) == 0) { smax[i >> 5] = mx; smin[i >> 5] = mn; }
    __syncthreads();
    if (i == 0) {
        float lmax = fmaxf(fmaxf(smax[0], smax[1]), fmaxf(smax[2], smax[3]));
        float lmin = fminf(fminf(smin[0], smin[1]), fminf(smin[2], smin[3]));
        s_x0 = (lmin > 0.f) ? 2.f / (lmax + lmin) : 1.f / lmax;
    }
    __syncthreads();
    float x0 = s_x0;
    for (int e = i; e < 128 * 128; e += 128) {
        int p = e >> 7, q = e & 127;
        g_NSa[e] = 2.f * x0 * ((p == q) ? 1.f : 0.f) - x0 * x0 * g_S[e];
    }
}
__global__ void __launch_bounds__(256)
ns_step(const float* __restrict__ X, float* __restrict__ Xn) {
    __shared__ float xr[2][128];
    __shared__ float t[2][128];
    int tid = threadIdx.x;
    int r0 = blockIdx.x * 2;
    int rr = tid >> 7, j = tid & 127;
    xr[rr][j] = X[(r0 + rr) * 128 + j];
    __syncthreads();
    float acc = 0.f;
#pragma unroll 8
    for (int k = 0; k < 128; k++)
        acc = fmaf(xr[rr][k], g_S[k * 128 + j], acc);
    t[rr][j] = acc;
    __syncthreads();
    float acc2 = 0.f;
#pragma unroll 8
    for (int k = 0; k < 128; k++)
        acc2 = fmaf(t[rr][k], X[k * 128 + j], acc2);
    Xn[(r0 + rr) * 128 + j] = 2.f * xr[rr][j] - acc2;
}

// fused: blocks 0-127 -> HT rows; blocks 128-255 -> d = Sinv @ c
__global__ void HT_d(const float* __restrict__ Sinv,
                     const float* __restrict__ log_rho) {
    int tid = threadIdx.x;
    if (blockIdx.x < 128) {
        __shared__ float gk[128];
        int j = tid, k = blockIdx.x;
        float rho = expf(log_rho[0]);
        gk[j] = g_G[k * 128 + j];
        __syncthreads();
        float acc = 0.f;
#pragma unroll 4
        for (int m = 0; m < 128; m++)
            acc = fmaf(Sinv[m * 128 + j], gk[m], acc);
        g_HT[k * 128 + j] = rho * (((j == k) ? 1.f : 0.f) - acc);
    } else {
        __shared__ float cb[8][128];
        int b0 = (blockIdx.x - 128) * 8;
#pragma unroll
        for (int bb = 0; bb < 8; bb++) {
            int b = b0 + bb;
            float pa = 0.f, pbv = 0.f;
#pragma unroll
            for (int sp = 0; sp < 8; sp++) {
                pa  += g_part[((size_t)sp * 2048 + 2 * b) * TM2 + tid];
                pbv += g_part[((size_t)sp * 2048 + 2 * b + 1) * TM2 + (tid ^ 64)];
            }
            cb[bb][tid] = (tid < 64) ? pa - pbv : pa + pbv;
        }
        __syncthreads();
        float acc[8];
#pragma unroll
        for (int bb = 0; bb < 8; bb++) acc[bb] = 0.f;
        for (int k = 0; k < 128; k++) {
            float sv = Sinv[k * 128 + tid];
#pragma unroll
            for (int bb = 0; bb < 8; bb++) acc[bb] = fmaf(sv, cb[bb][k], acc[bb]);
        }
#pragma unroll
        for (int bb = 0; bb < 8; bb++)
            g_d[(b0 + bb) * TM2 + tid] = acc[bb];
    }
}

// s for iter 0: w = y - u_in; s = H w - d (frag output); init g_u
__global__ void s_init(const float* __restrict__ y,
                       const float* __restrict__ u_in) {
    __shared__ float w[8][128];
    int tid = threadIdx.x;
    int b0 = blockIdx.x * 8;
#pragma unroll
    for (int bb = 0; bb < 8; bb++) {
        float uv = u_in[(b0 + bb) * TM2 + tid];
        g_u[(b0 + bb) * TM2 + tid] = uv;
        w[bb][tid] = y[(b0 + bb) * TM2 + tid] - uv;
    }
    __syncthreads();
    float acc[8];
#pragma unroll
    for (int bb = 0; bb < 8; bb++) acc[bb] = 0.f;
    for (int k = 0; k < 128; k++) {
        float h = g_HT[k * 128 + tid];
#pragma unroll
        for (int bb = 0; bb < 8; bb++) acc[bb] = fmaf(h, w[bb][k], acc[bb]);
    }
    __syncthreads();
#pragma unroll
    for (int bb = 0; bb < 8; bb++)
        w[bb][tid] = acc[bb] - g_d[(b0 + bb) * TM2 + tid];
    __syncthreads();
    if (tid < 64) {
#pragma unroll
        for (int bb = 0; bb < 8; bb++) {
            int b = b0 + bb;
            int row = b & 127, rtile = b >> 7, kp = tid;
            uint32_t h, l;
            split_pack(w[bb][2 * kp], w[bb][2 * kp + 1], h, l);
            uint32_t ad = (uint32_t)rtile * 8192 + a_addr(row, kp);
            g_sfh[ad] = h;
            g_sfl[ad] = l;
        }
    }
}

// fused: P = reduce(partials); zu update; s(frag) for next iter / final u out
__global__ void zus(const float* __restrict__ y,
                    const float* __restrict__ log_eps, int compute_s,
                    float* __restrict__ uout) {
    __shared__ float red[4];
    __shared__ float w[128];
    int b = blockIdx.x;
    int j = threadIdx.x;
    float eps = expf(log_eps[0]);
    float Pv = 0.f;
#pragma unroll
    for (int ks = 0; ks < NSPLIT; ks++)
        Pv += g_part[((size_t)ks * BATCH + b) * TM2 + j];
    float uv = g_u[b * TM2 + j];
    float yv = y[b * TM2 + j];
    float v = Pv + uv - yv;
    float t = v * v;
#pragma unroll
    for (int o = 16; o > 0; o >>= 1) t += __shfl_down_sync(0xffffffffu, t, o);
    if ((j & 31) == 0) red[j >> 5] = t;
    __syncthreads();
    float nrm = sqrtf(red[0] + red[1] + red[2] + red[3]);
    float scale = fminf(1.f, eps / (nrm + 1e-12f));
    float zv = yv + v * scale;
    float un = uv + Pv - zv;
    if (compute_s) {
        g_u[b * TM2 + j] = un;
        w[j] = zv - un;
        __syncthreads();
        float acc = 0.f;
#pragma unroll 4
        for (int k = 0; k < 128; k++)
            acc = fmaf(g_HT[k * 128 + j], w[k], acc);
        float sval = acc - g_d[b * TM2 + j];
        __syncthreads();
        w[j] = sval;
        __syncthreads();
        if (j < 64) {
            int row = b & 127, rtile = b >> 7, kp = j;
            uint32_t h, l;
            split_pack(w[2 * kp], w[2 * kp + 1], h, l);
            uint32_t ad = (uint32_t)rtile * 8192 + a_addr(row, kp);
            g_sfh[ad] = h;
            g_sfl[ad] = l;
        }
    } else {
        uout[(size_t)BATCH * 2 * NDIM + b * TM2 + j] = un;
    }
}

// ---------------- launch ----------------------------------------------------
extern "C" void kernel_launch(void* const* d_in, const int* in_sizes, int n_in,
                              void* d_out, int out_size) {
    const float* rn   = (const float*)d_in[0];
    const float* y    = (const float*)d_in[1];
    const float* u_in = (const float*)d_in[2];
    const float* A    = (const float*)d_in[3];
    const float* lrho = (const float*)d_in[4];
    const float* leps = (const float*)d_in[5];
    float* out = (float*)d_out;
    (void)in_sizes; (void)n_in; (void)out_size;

    float *dM, *dPart, *dNSa, *dNSb;
    uint32_t *dWafh, *dWafl;
    cudaGetSymbolAddress((void**)&dM,    g_M);
    cudaGetSymbolAddress((void**)&dPart, g_part);
    cudaGetSymbolAddress((void**)&dNSa,  g_NSa);
    cudaGetSymbolAddress((void**)&dNSb,  g_NSb);
    cudaGetSymbolAddress((void**)&dWafh, g_Wafh);
    cudaGetSymbolAddress((void**)&dWafl, g_Wafl);

    static int attr_set = 0;
    if (!attr_set) {
        cudaFuncSetAttribute(nt2, cudaFuncAttributeMaxDynamicSharedMemorySize,
                             NT_SMEM_BYTES);
        cudaFuncSetAttribute(fused_xp,
                             cudaFuncAttributeMaxDynamicSharedMemorySize,
                             FX_SMEM_BYTES);
        cudaFuncSetAttribute(proj_rn,
                             cudaFuncAttributeMaxDynamicSharedMemorySize,
                             PR_SMEM_BYTES);
        cudaFuncSetAttribute(to_afrag,
                             cudaFuncAttributeMaxDynamicSharedMemorySize,
                             AF_SMEM_BYTES);
        attr_set = 1;
    }

    // W fragment layouts + W A-frag conversion
    wf_nn<<<(8192 * 64 + 255) / 256, 256>>>(A);
    wf_nt<<<(128 * 4096 + 255) / 256, 256>>>(A);
    to_afrag<<<dim3(1, 64), 256, AF_SMEM_BYTES>>>(A, dWafh, dWafl);

    // M = W W^T (32-way split), then S
    nt2<<<dim3(1, 32, 2), 256, NT_SMEM_BYTES>>>(dWafh, dWafl, dPart, 128, 2);
    reduce_nt<<<(4096 + 255) / 256, 256>>>((const float4*)dPart,
                                           (float4*)dM, 4096, 32);
    build_S<<<64, 256>>>(lrho);

    // Newton-Schulz inverse: X1 + 3 fused steps
    gersh_initX1<<<1, 128>>>();
    ns_step<<<64, 256>>>(dNSa, dNSb);
    ns_step<<<64, 256>>>(dNSb, dNSa);
    ns_step<<<64, 256>>>(dNSa, dNSb);
    const float* Sinv = dNSb;

    // rn projections (inline convert, 8 splits), fused HT + d, s for iter 0
    proj_rn<<<dim3(16, 8), 512, PR_SMEM_BYTES>>>(rn, dPart);
    HT_d<<<256, 128>>>(Sinv, lrho);
    s_init<<<128, 128>>>(y, u_in);

    for (int it = 0; it < 3; it++) {
        int fin = (it == 2);
        fused_xp<<<dim3(NSPLIT, 8), 512, FX_SMEM_BYTES>>>(rn, out, fin, dPart);
        zus<<<BATCH, 128>>>(y, leps, it < 2, out);
    }
}